// round 3
// baseline (speedup 1.0000x reference)
#include <cuda_runtime.h>

// ---------------------------------------------------------------------------
// 3-layer Elman RNN: (B=8192, T=64) 84 -> 128 -> 128 -> 84
// h_t = tanh(x_t W_ih^T + b_ih + b_hh + h_{t-1} W_hh^T)
//
// Plan per layer:
//   1) proj_kernel: XP[b,t,:] = X[b,t,:] @ W_ih^T + (b_ih+b_hh)   (big GEMM)
//   2) rnn_kernel : sequential scan over t with W_hh and h tile in smem,
//                   in-place over the XP buffer (XP[b,t] consumed at step t).
// All inner loops use packed fma.rn.f32x2 (2 fp32 FMA per issued instr).
// ---------------------------------------------------------------------------

namespace {
constexpr int B  = 8192;
constexpr int T  = 64;
constexpr int IN = 84;
constexpr int H1 = 128;
constexpr int H2 = 84;
constexpr long M = (long)B * T;   // 524288 rows
}

// Scratch ping-pong buffers (device globals: allocation-free rule)
__device__ float g_bufA[(size_t)M * H1];
__device__ float g_bufB[(size_t)M * H1];

// Pre-transposed / padded weights & fused biases
__device__ float g_wih0t[IN * H1];    // [k=0..83 ][n=0..127]
__device__ float g_whh0t[H1 * H1];    // [k][j]
__device__ float g_b0[H1];
__device__ float g_wih1t[H1 * H1];
__device__ float g_whh1t[H1 * H1];
__device__ float g_b1[H1];
__device__ float g_wih2t[H1 * 96];    // [k=0..127][n=0..95] (n>=84 zero)
__device__ float g_whh2t[IN * 96];    // [k=0..83 ][j=0..95] (j>=84 zero)
__device__ float g_b2[96];

// ---------------- packed f32x2 helpers ----------------
__device__ __forceinline__ unsigned long long pk2(float lo, float hi) {
    unsigned long long r;
    asm("mov.b64 %0, {%1, %2};" : "=l"(r) : "f"(lo), "f"(hi));
    return r;
}
__device__ __forceinline__ void upk2(float& lo, float& hi, unsigned long long v) {
    asm("mov.b64 {%0, %1}, %2;" : "=f"(lo), "=f"(hi) : "l"(v));
}
__device__ __forceinline__ void fma2(unsigned long long& d, unsigned long long a,
                                     unsigned long long b) {
    asm("fma.rn.f32x2 %0, %1, %2, %0;" : "+l"(d) : "l"(a), "l"(b));
}

// ---------------- weight prep (transpose + pad + bias fuse) ----------------
__global__ void prep_kernel(
    const float* __restrict__ wih0, const float* __restrict__ whh0,
    const float* __restrict__ bi0,  const float* __restrict__ bh0,
    const float* __restrict__ wih1, const float* __restrict__ whh1,
    const float* __restrict__ bi1,  const float* __restrict__ bh1,
    const float* __restrict__ wih2, const float* __restrict__ whh2,
    const float* __restrict__ bi2,  const float* __restrict__ bh2)
{
    int tid = blockIdx.x * blockDim.x + threadIdx.x;
    int nt  = gridDim.x * blockDim.x;
    for (int i = tid; i < IN * H1; i += nt) {
        int k = i / H1, n = i % H1;
        g_wih0t[i] = wih0[n * IN + k];
    }
    for (int i = tid; i < H1 * H1; i += nt) {
        int k = i / H1, n = i % H1;
        g_whh0t[i] = whh0[n * H1 + k];
        g_wih1t[i] = wih1[n * H1 + k];
        g_whh1t[i] = whh1[n * H1 + k];
    }
    for (int i = tid; i < H1 * 96; i += nt) {
        int k = i / 96, n = i % 96;
        g_wih2t[i] = (n < H2) ? wih2[n * H1 + k] : 0.f;
    }
    for (int i = tid; i < IN * 96; i += nt) {
        int k = i / 96, n = i % 96;
        g_whh2t[i] = (n < H2) ? whh2[n * H2 + k] : 0.f;
    }
    for (int i = tid; i < H1; i += nt) {
        g_b0[i] = bi0[i] + bh0[i];
        g_b1[i] = bi1[i] + bh1[i];
    }
    for (int i = tid; i < 96; i += nt)
        g_b2[i] = (i < H2) ? (bi2[i] + bh2[i]) : 0.f;
}

// ---------------- input projection GEMM ----------------
// Y[m, 0..N) = X[m, 0..K) @ Wt[K, NP] + bias   (Wt k-major, NP-padded)
// Block: 128 M-rows x NP cols, threads = (NP/8)*(128/8), thread tile 8x8.
template<int K, int N, int NP>
__global__ void __launch_bounds__(NP * 2)
proj_kernel(const float* __restrict__ X, const float* __restrict__ Wt,
            const float* __restrict__ bias, float* __restrict__ Y)
{
    constexpr int KS = (K % 32 == 0) ? K + 4 : K;  // smem row stride (bank pad)
    extern __shared__ float sm[];
    float* xs = sm;               // [128][KS]
    float* ws = xs + 128 * KS;    // [K][NP]
    float* bs = ws + K * NP;      // [NP]

    const int tid  = threadIdx.x;
    const int nthr = NP * 2;
    const size_t m0 = (size_t)blockIdx.x * 128;

    {
        const float4* Xg = (const float4*)(X + m0 * K);
        for (int i = tid; i < 128 * (K / 4); i += nthr) {
            int r = i / (K / 4), kq = i % (K / 4);
            ((float4*)(xs + r * KS))[kq] = Xg[i];
        }
        const float4* Wg = (const float4*)Wt;
        float4* dw = (float4*)ws;
        for (int i = tid; i < K * NP / 4; i += nthr) dw[i] = Wg[i];
        for (int i = tid; i < NP; i += nthr) bs[i] = bias[i];
    }
    __syncthreads();

    const int jg = tid % (NP / 8);
    const int ig = tid / (NP / 8);
    const int j0 = jg * 8;
    const int r0 = ig * 8;

    unsigned long long acc[8][4];
#pragma unroll
    for (int q = 0; q < 4; q++) {
        unsigned long long bq = pk2(bs[j0 + 2 * q], bs[j0 + 2 * q + 1]);
#pragma unroll
        for (int i = 0; i < 8; i++) acc[i][q] = bq;
    }

#pragma unroll 4
    for (int k = 0; k < K; k++) {
        const ulonglong2 wA = *(const ulonglong2*)&ws[k * NP + j0];
        const ulonglong2 wB = *(const ulonglong2*)&ws[k * NP + j0 + 4];
#pragma unroll
        for (int i = 0; i < 8; i++) {
            float v = xs[(r0 + i) * KS + k];
            unsigned long long xv = pk2(v, v);
            fma2(acc[i][0], xv, wA.x);
            fma2(acc[i][1], xv, wA.y);
            fma2(acc[i][2], xv, wB.x);
            fma2(acc[i][3], xv, wB.y);
        }
    }

#pragma unroll
    for (int i = 0; i < 8; i++) {
        float* yr = Y + (m0 + r0 + i) * N;
#pragma unroll
        for (int q = 0; q < 4; q++) {
            float lo, hi;
            upk2(lo, hi, acc[i][q]);
            int n = j0 + 2 * q;
            if (N == NP) {
                *(float2*)&yr[n] = make_float2(lo, hi);
            } else {
                if (n < N)     yr[n]     = lo;
                if (n + 1 < N) yr[n + 1] = hi;
            }
        }
    }
}

// ---------------- recurrence scan ----------------
// In-place over XP: at step t reads XP[b, t, :], writes Yout[b, t, :].
// Block owns BB=64 batch rows; W_hh and h tile live in smem all T steps.
template<int H, int HP, int BB>
__global__ void __launch_bounds__((HP / 8) * (BB / 4))
rnn_kernel(const float* __restrict__ XP, const float* __restrict__ Wt,
           float* __restrict__ Yout)
{
    constexpr int HS = HP + 4;             // h-tile row stride (bank pad)
    extern __shared__ float sm[];
    float* ws = sm;                        // [H][HP]
    float* hs = ws + H * HP;               // [BB][HS]

    const int tid  = threadIdx.x;
    const int nthr = (HP / 8) * (BB / 4);
    const size_t b0 = (size_t)blockIdx.x * BB;

    {
        const float4* Wg = (const float4*)Wt;
        float4* dw = (float4*)ws;
        for (int i = tid; i < H * HP / 4; i += nthr) dw[i] = Wg[i];
        float4* dh = (float4*)hs;
        for (int i = tid; i < BB * HS / 4; i += nthr)
            dh[i] = make_float4(0.f, 0.f, 0.f, 0.f);
    }
    __syncthreads();

    const int jg = tid % (HP / 8);
    const int ig = tid / (HP / 8);
    const int j0 = jg * 8;
    const int r0 = ig * 4;

    float xp[4][8];
#pragma unroll
    for (int i = 0; i < 4; i++) {
        const float* p = XP + ((b0 + r0 + i) * T + 0) * H + j0;
        float4 a = (j0 + 4 <= H) ? *(const float4*)p       : make_float4(0,0,0,0);
        float4 b = (j0 + 8 <= H) ? *(const float4*)(p + 4) : make_float4(0,0,0,0);
        xp[i][0]=a.x; xp[i][1]=a.y; xp[i][2]=a.z; xp[i][3]=a.w;
        xp[i][4]=b.x; xp[i][5]=b.y; xp[i][6]=b.z; xp[i][7]=b.w;
    }

    for (int t = 0; t < T; t++) {
        // prefetch next step's xp while the k-loop runs
        float xn[4][8];
        if (t + 1 < T) {
#pragma unroll
            for (int i = 0; i < 4; i++) {
                const float* p = XP + ((b0 + r0 + i) * T + (t + 1)) * H + j0;
                float4 a = (j0 + 4 <= H) ? *(const float4*)p       : make_float4(0,0,0,0);
                float4 b = (j0 + 8 <= H) ? *(const float4*)(p + 4) : make_float4(0,0,0,0);
                xn[i][0]=a.x; xn[i][1]=a.y; xn[i][2]=a.z; xn[i][3]=a.w;
                xn[i][4]=b.x; xn[i][5]=b.y; xn[i][6]=b.z; xn[i][7]=b.w;
            }
        } else {
#pragma unroll
            for (int i = 0; i < 4; i++)
#pragma unroll
                for (int c = 0; c < 8; c++) xn[i][c] = 0.f;
        }

        unsigned long long acc[4][4];
#pragma unroll
        for (int i = 0; i < 4; i++)
#pragma unroll
            for (int q = 0; q < 4; q++)
                acc[i][q] = pk2(xp[i][2 * q], xp[i][2 * q + 1]);

#pragma unroll 4
        for (int k = 0; k < H; k++) {
            const ulonglong2 wA = *(const ulonglong2*)&ws[k * HP + j0];
            const ulonglong2 wB = *(const ulonglong2*)&ws[k * HP + j0 + 4];
#pragma unroll
            for (int i = 0; i < 4; i++) {
                float v = hs[(r0 + i) * HS + k];
                unsigned long long hv = pk2(v, v);
                fma2(acc[i][0], hv, wA.x);
                fma2(acc[i][1], hv, wA.y);
                fma2(acc[i][2], hv, wB.x);
                fma2(acc[i][3], hv, wB.y);
            }
        }

        float out[4][8];
#pragma unroll
        for (int i = 0; i < 4; i++)
#pragma unroll
            for (int q = 0; q < 4; q++) {
                float lo, hi;
                upk2(lo, hi, acc[i][q]);
                out[i][2 * q]     = tanhf(lo);
                out[i][2 * q + 1] = tanhf(hi);
            }

        __syncthreads();   // all reads of hs (step t) complete
#pragma unroll
        for (int i = 0; i < 4; i++) {
            float* hr = hs + (r0 + i) * HS + j0;
            float* yr = Yout + ((b0 + r0 + i) * T + t) * H + j0;
#pragma unroll
            for (int c = 0; c < 8; c++) {
                if (j0 + c < H) {
                    hr[c] = out[i][c];
                    yr[c] = out[i][c];
                }
            }
        }
        __syncthreads();   // hs ready for step t+1

#pragma unroll
        for (int i = 0; i < 4; i++)
#pragma unroll
            for (int c = 0; c < 8; c++) xp[i][c] = xn[i][c];
    }
}

// ---------------- launch ----------------
extern "C" void kernel_launch(void* const* d_in, const int* in_sizes, int n_in,
                              void* d_out, int out_size)
{
    (void)in_sizes; (void)n_in; (void)out_size;
    const float* x    = (const float*)d_in[0];
    const float* wih0 = (const float*)d_in[1];
    const float* whh0 = (const float*)d_in[2];
    const float* bi0  = (const float*)d_in[3];
    const float* bh0  = (const float*)d_in[4];
    const float* wih1 = (const float*)d_in[5];
    const float* whh1 = (const float*)d_in[6];
    const float* bi1  = (const float*)d_in[7];
    const float* bh1  = (const float*)d_in[8];
    const float* wih2 = (const float*)d_in[9];
    const float* whh2 = (const float*)d_in[10];
    const float* bi2  = (const float*)d_in[11];
    const float* bh2  = (const float*)d_in[12];
    float* out = (float*)d_out;

    void* p;
    cudaGetSymbolAddress(&p, g_bufA);   float* bufA  = (float*)p;
    cudaGetSymbolAddress(&p, g_bufB);   float* bufB  = (float*)p;
    cudaGetSymbolAddress(&p, g_wih0t);  float* W0i   = (float*)p;
    cudaGetSymbolAddress(&p, g_whh0t);  float* W0h   = (float*)p;
    cudaGetSymbolAddress(&p, g_b0);     float* Bs0   = (float*)p;
    cudaGetSymbolAddress(&p, g_wih1t);  float* W1i   = (float*)p;
    cudaGetSymbolAddress(&p, g_whh1t);  float* W1h   = (float*)p;
    cudaGetSymbolAddress(&p, g_b1);     float* Bs1   = (float*)p;
    cudaGetSymbolAddress(&p, g_wih2t);  float* W2i   = (float*)p;
    cudaGetSymbolAddress(&p, g_whh2t);  float* W2h   = (float*)p;
    cudaGetSymbolAddress(&p, g_b2);     float* Bs2   = (float*)p;

    // dynamic smem sizes (must match kernel layouts incl. padded strides)
    const int smem_p0 = (128 * 84  + 84  * 128 + 128) * 4;   // K=84  KS=84
    const int smem_p1 = (128 * 132 + 128 * 128 + 128) * 4;   // K=128 KS=132
    const int smem_p2 = (128 * 132 + 128 * 96  + 96 ) * 4;   // K=128 KS=132
    const int smem_r1 = (128 * 128 + 64 * 132) * 4;          // H=128 HS=132
    const int smem_r2 = (84  * 96  + 64 * 100) * 4;          // H=84  HS=100

    cudaFuncSetAttribute((const void*)proj_kernel<84, 128, 128>,
                         cudaFuncAttributeMaxDynamicSharedMemorySize, smem_p0);
    cudaFuncSetAttribute((const void*)proj_kernel<128, 128, 128>,
                         cudaFuncAttributeMaxDynamicSharedMemorySize, smem_p1);
    cudaFuncSetAttribute((const void*)proj_kernel<128, 84, 96>,
                         cudaFuncAttributeMaxDynamicSharedMemorySize, smem_p2);
    cudaFuncSetAttribute((const void*)rnn_kernel<128, 128, 64>,
                         cudaFuncAttributeMaxDynamicSharedMemorySize, smem_r1);
    cudaFuncSetAttribute((const void*)rnn_kernel<84, 96, 64>,
                         cudaFuncAttributeMaxDynamicSharedMemorySize, smem_r2);

    prep_kernel<<<96, 256>>>(wih0, whh0, bi0, bh0,
                             wih1, whh1, bi1, bh1,
                             wih2, whh2, bi2, bh2);

    const int mblocks = (int)(M / 128);   // 4096
    const int rblocks = B / 64;           // 128

    // Layer 0: x (K=84) -> bufA, scan in-place
    proj_kernel<84, 128, 128><<<mblocks, 256, smem_p0>>>(x, W0i, Bs0, bufA);
    rnn_kernel<128, 128, 64><<<rblocks, 256, smem_r1>>>(bufA, W0h, bufA);

    // Layer 1: bufA -> bufB, scan in-place
    proj_kernel<128, 128, 128><<<mblocks, 256, smem_p1>>>(bufA, W1i, Bs1, bufB);
    rnn_kernel<128, 128, 64><<<rblocks, 256, smem_r1>>>(bufB, W1h, bufB);

    // Layer 2: bufB -> bufA (stride 84), scan writes final output
    proj_kernel<128, 84, 96><<<mblocks, 192, smem_p2>>>(bufB, W2i, Bs2, bufA);
    rnn_kernel<84, 96, 64><<<rblocks, 192, smem_r2>>>(bufA, W2h, out);
}

// round 6
// speedup vs baseline: 1.0656x; 1.0656x over previous
#include <cuda_runtime.h>

// ---------------------------------------------------------------------------
// 3-layer Elman RNN: (B=8192, T=64) 84 -> 128 -> 128 -> 84
// h_t = tanh(x_t W_ih^T + b_ih + b_hh + h_{t-1} W_hh^T)
//
// v3: - all kernels run 2 CTAs/SM (smem chunked below 114KB, launch_bounds)
//     - scalar GEMM operand stored in smem as duplicated {v,v} 64-bit pairs:
//       LDS.128 feeds two k-steps of fma.rn.f32x2 with zero broadcast MOVs
//     - rnn grid 256 blocks (BB=32) -> no idle SMs, single wave
//     - fast tanh via ex2.approx + rcp.approx
// ---------------------------------------------------------------------------

namespace {
constexpr int B  = 8192;
constexpr int T  = 64;
constexpr int IN = 84;
constexpr int H1 = 128;
constexpr int H2 = 84;
constexpr long M = (long)B * T;   // 524288 rows
}

// Scratch ping-pong buffers (device globals: allocation-free rule)
__device__ float g_bufA[(size_t)M * H1];
__device__ float g_bufB[(size_t)M * H1];

// Pre-transposed / padded weights & fused biases
__device__ float g_wih0t[IN * H1];    // [k][n]
__device__ float g_whh0t[H1 * H1];
__device__ float g_b0[H1];
__device__ float g_wih1t[H1 * H1];
__device__ float g_whh1t[H1 * H1];
__device__ float g_b1[H1];
__device__ float g_wih2t[H1 * 96];    // n>=84 zero
__device__ float g_whh2t[IN * 96];    // j>=84 zero
__device__ float g_b2[96];

// ---------------- packed f32x2 helpers ----------------
__device__ __forceinline__ unsigned long long pk2(float lo, float hi) {
    unsigned long long r;
    asm("mov.b64 %0, {%1, %2};" : "=l"(r) : "f"(lo), "f"(hi));
    return r;
}
__device__ __forceinline__ void upk2(float& lo, float& hi, unsigned long long v) {
    asm("mov.b64 {%0, %1}, %2;" : "=f"(lo), "=f"(hi) : "l"(v));
}
__device__ __forceinline__ void fma2(unsigned long long& d, unsigned long long a,
                                     unsigned long long b) {
    asm("fma.rn.f32x2 %0, %1, %2, %0;" : "+l"(d) : "l"(a), "l"(b));
}

// tanh(x) = 1 - 2/(exp(2x)+1); ex2/rcp approx ~1e-6 rel err, saturates cleanly.
__device__ __forceinline__ float fast_tanh(float x) {
    float e, r;
    asm("ex2.approx.f32 %0, %1;" : "=f"(e) : "f"(x * 2.885390081777927f));
    asm("rcp.approx.f32 %0, %1;" : "=f"(r) : "f"(e + 1.0f));
    return fmaf(-2.0f, r, 1.0f);
}

// ---------------- weight prep (transpose + pad + bias fuse) ----------------
__global__ void prep_kernel(
    const float* __restrict__ wih0, const float* __restrict__ whh0,
    const float* __restrict__ bi0,  const float* __restrict__ bh0,
    const float* __restrict__ wih1, const float* __restrict__ whh1,
    const float* __restrict__ bi1,  const float* __restrict__ bh1,
    const float* __restrict__ wih2, const float* __restrict__ whh2,
    const float* __restrict__ bi2,  const float* __restrict__ bh2)
{
    int tid = blockIdx.x * blockDim.x + threadIdx.x;
    int nt  = gridDim.x * blockDim.x;
    for (int i = tid; i < IN * H1; i += nt) {
        int k = i / H1, n = i % H1;
        g_wih0t[i] = wih0[n * IN + k];
    }
    for (int i = tid; i < H1 * H1; i += nt) {
        int k = i / H1, n = i % H1;
        g_whh0t[i] = whh0[n * H1 + k];
        g_wih1t[i] = wih1[n * H1 + k];
        g_whh1t[i] = whh1[n * H1 + k];
    }
    for (int i = tid; i < H1 * 96; i += nt) {
        int k = i / 96, n = i % 96;
        g_wih2t[i] = (n < H2) ? wih2[n * H1 + k] : 0.f;
    }
    for (int i = tid; i < IN * 96; i += nt) {
        int k = i / 96, n = i % 96;
        g_whh2t[i] = (n < H2) ? whh2[n * H2 + k] : 0.f;
    }
    for (int i = tid; i < H1; i += nt) {
        g_b0[i] = bi0[i] + bh0[i];
        g_b1[i] = bi1[i] + bh1[i];
    }
    for (int i = tid; i < 96; i += nt)
        g_b2[i] = (i < H2) ? (bi2[i] + bh2[i]) : 0.f;
}

// ---------------- input projection GEMM ----------------
// Y[m,0..N) = X[m,0..K) @ Wt[K,NP] + bias. Block tile 128 rows x NP cols.
// X staged in K-chunks of CH, stored DUPLICATED ({v,v} u64 pairs) in smem.
template<int K, int N, int NP, int CH, int NTHR>
__global__ void __launch_bounds__(NTHR, 2)
proj_kernel(const float* __restrict__ X, const float* __restrict__ Wt,
            const float* __restrict__ bias, float* __restrict__ Y)
{
    constexpr int NCH = K / CH;
    constexpr int VEC = (CH % 8 == 0) ? 4 : 2;     // global load width
    constexpr int TOT = 128 * CH / VEC;            // vec loads per chunk
    constexpr int NLD = (TOT + NTHR - 1) / NTHR;

    extern __shared__ float sm[];
    float* ws = sm;                                            // [K][NP]
    unsigned long long* xd = (unsigned long long*)(ws + K * NP); // [128][CH] dup
    float* bs = (float*)(xd + 128 * CH);                       // [NP]

    const int tid = threadIdx.x;
    const size_t m0 = (size_t)blockIdx.x * 128;
    const float* Xg = X + m0 * K;

    // cooperative load: weights + bias
    for (int i = tid; i < K * NP / 4; i += NTHR)
        ((float4*)ws)[i] = ((const float4*)Wt)[i];
    for (int i = tid; i < NP; i += NTHR) bs[i] = bias[i];

    const int jg = tid % (NP / 8);
    const int ig = tid / (NP / 8);
    const int j0 = jg * 8;
    const int r0 = ig * 8;

    float pf[NLD][VEC];
    // prefetch chunk 0
    {
#pragma unroll
        for (int it = 0; it < NLD; it++) {
            int idx = tid + it * NTHR;
            if ((TOT % NTHR == 0) || idx < TOT) {
                int e   = idx * VEC;
                int row = e / CH, kc = e % CH;
                const float* p = Xg + (size_t)row * K + kc;
                if (VEC == 4) {
                    float4 v = *(const float4*)p;
                    pf[it][0] = v.x; pf[it][1] = v.y;
                    pf[it][2] = v.z; pf[it][3] = v.w;
                } else {
                    float2 v = *(const float2*)p;
                    pf[it][0] = v.x; pf[it][1] = v.y;
                }
            }
        }
    }

    __syncthreads();   // ws, bs visible

    unsigned long long acc[8][4];
#pragma unroll
    for (int q = 0; q < 4; q++) {
        unsigned long long bq = pk2(bs[j0 + 2 * q], bs[j0 + 2 * q + 1]);
#pragma unroll
        for (int i = 0; i < 8; i++) acc[i][q] = bq;
    }

    for (int c = 0; c < NCH; c++) {
        // store prefetched chunk, duplicated
#pragma unroll
        for (int it = 0; it < NLD; it++) {
            int idx = tid + it * NTHR;
            if ((TOT % NTHR == 0) || idx < TOT) {
#pragma unroll
                for (int v = 0; v < VEC; v++)
                    xd[idx * VEC + v] = pk2(pf[it][v], pf[it][v]);
            }
        }
        __syncthreads();

        // prefetch next chunk (LDGs overlap compute below)
        if (c + 1 < NCH) {
#pragma unroll
            for (int it = 0; it < NLD; it++) {
                int idx = tid + it * NTHR;
                if ((TOT % NTHR == 0) || idx < TOT) {
                    int e   = idx * VEC;
                    int row = e / CH, kc = e % CH;
                    const float* p = Xg + (size_t)row * K + (c + 1) * CH + kc;
                    if (VEC == 4) {
                        float4 v = *(const float4*)p;
                        pf[it][0] = v.x; pf[it][1] = v.y;
                        pf[it][2] = v.z; pf[it][3] = v.w;
                    } else {
                        float2 v = *(const float2*)p;
                        pf[it][0] = v.x; pf[it][1] = v.y;
                    }
                }
            }
        }

        // compute this chunk: k-pairs, zero broadcast MOVs
#pragma unroll 4
        for (int kk = 0; kk < CH; kk += 2) {
            const int k = c * CH + kk;
            const ulonglong2 wA = *(const ulonglong2*)&ws[k * NP + j0];
            const ulonglong2 wB = *(const ulonglong2*)&ws[k * NP + j0 + 4];
            const ulonglong2 wC = *(const ulonglong2*)&ws[(k + 1) * NP + j0];
            const ulonglong2 wD = *(const ulonglong2*)&ws[(k + 1) * NP + j0 + 4];
#pragma unroll
            for (int i = 0; i < 8; i++) {
                const ulonglong2 xv = *(const ulonglong2*)&xd[(r0 + i) * CH + kk];
                fma2(acc[i][0], xv.x, wA.x);
                fma2(acc[i][1], xv.x, wA.y);
                fma2(acc[i][2], xv.x, wB.x);
                fma2(acc[i][3], xv.x, wB.y);
                fma2(acc[i][0], xv.y, wC.x);
                fma2(acc[i][1], xv.y, wC.y);
                fma2(acc[i][2], xv.y, wD.x);
                fma2(acc[i][3], xv.y, wD.y);
            }
        }
        if (c + 1 < NCH) __syncthreads();   // xd reads done before next store
    }

    // epilogue
#pragma unroll
    for (int i = 0; i < 8; i++) {
        float* yr = Y + (m0 + r0 + i) * N;
        float o[8];
#pragma unroll
        for (int q = 0; q < 4; q++) upk2(o[2 * q], o[2 * q + 1], acc[i][q]);
        if (N == NP) {
            *(float4*)&yr[j0]     = make_float4(o[0], o[1], o[2], o[3]);
            *(float4*)&yr[j0 + 4] = make_float4(o[4], o[5], o[6], o[7]);
        } else {
#pragma unroll
            for (int c2 = 0; c2 < 8; c2++)
                if (j0 + c2 < N) yr[j0 + c2] = o[c2];
        }
    }
}

// ---------------- recurrence scan ----------------
// Block owns BB=32 batch rows for all T steps. W_hh in smem; h kept in smem
// DUPLICATED ({v,v} pairs) so the k-loop needs no broadcast MOVs.
template<int H, int HP, int BB>
__global__ void __launch_bounds__((HP / 8) * (BB / 4), 2)
rnn_kernel(const float* __restrict__ XP, const float* __restrict__ Wt,
           float* __restrict__ Yout)
{
    constexpr int NTHR = (HP / 8) * (BB / 4);
    extern __shared__ float sm[];
    float* ws = sm;                                             // [H][HP]
    unsigned long long* hd = (unsigned long long*)(ws + H * HP); // [BB][H] dup

    const int tid = threadIdx.x;
    const size_t b0 = (size_t)blockIdx.x * BB;

    for (int i = tid; i < H * HP / 4; i += NTHR)
        ((float4*)ws)[i] = ((const float4*)Wt)[i];
    for (int i = tid; i < BB * H; i += NTHR) hd[i] = 0ull;
    __syncthreads();

    const int jg = tid % (HP / 8);
    const int ig = tid / (HP / 8);
    const int j0 = jg * 8;
    const int r0 = ig * 4;

    float xp[4][8];
#pragma unroll
    for (int i = 0; i < 4; i++) {
        const float* p = XP + ((b0 + r0 + i) * T + 0) * H + j0;
        float4 a = *(const float4*)p;
        float4 b = *(const float4*)(p + 4);
        xp[i][0]=a.x; xp[i][1]=a.y; xp[i][2]=a.z; xp[i][3]=a.w;
        xp[i][4]=b.x; xp[i][5]=b.y; xp[i][6]=b.z; xp[i][7]=b.w;
    }

    for (int t = 0; t < T; t++) {
        // prefetch next step's xp (overlaps the k-loop)
        float xn[4][8];
        if (t + 1 < T) {
#pragma unroll
            for (int i = 0; i < 4; i++) {
                const float* p = XP + ((b0 + r0 + i) * T + (t + 1)) * H + j0;
                float4 a = *(const float4*)p;
                float4 b = *(const float4*)(p + 4);
                xn[i][0]=a.x; xn[i][1]=a.y; xn[i][2]=a.z; xn[i][3]=a.w;
                xn[i][4]=b.x; xn[i][5]=b.y; xn[i][6]=b.z; xn[i][7]=b.w;
            }
        } else {
#pragma unroll
            for (int i = 0; i < 4; i++)
#pragma unroll
                for (int c = 0; c < 8; c++) xn[i][c] = 0.f;
        }

        unsigned long long acc[4][4];
#pragma unroll
        for (int i = 0; i < 4; i++)
#pragma unroll
            for (int q = 0; q < 4; q++)
                acc[i][q] = pk2(xp[i][2 * q], xp[i][2 * q + 1]);

#pragma unroll 4
        for (int k = 0; k < H; k += 2) {
            const ulonglong2 wA = *(const ulonglong2*)&ws[k * HP + j0];
            const ulonglong2 wB = *(const ulonglong2*)&ws[k * HP + j0 + 4];
            const ulonglong2 wC = *(const ulonglong2*)&ws[(k + 1) * HP + j0];
            const ulonglong2 wD = *(const ulonglong2*)&ws[(k + 1) * HP + j0 + 4];
#pragma unroll
            for (int i = 0; i < 4; i++) {
                const ulonglong2 hv = *(const ulonglong2*)&hd[(r0 + i) * H + k];
                fma2(acc[i][0], hv.x, wA.x);
                fma2(acc[i][1], hv.x, wA.y);
                fma2(acc[i][2], hv.x, wB.x);
                fma2(acc[i][3], hv.x, wB.y);
                fma2(acc[i][0], hv.y, wC.x);
                fma2(acc[i][1], hv.y, wC.y);
                fma2(acc[i][2], hv.y, wD.x);
                fma2(acc[i][3], hv.y, wD.y);
            }
        }

        float out[4][8];
#pragma unroll
        for (int i = 0; i < 4; i++)
#pragma unroll
            for (int q = 0; q < 4; q++) {
                float lo, hi;
                upk2(lo, hi, acc[i][q]);
                out[i][2 * q]     = fast_tanh(lo);
                out[i][2 * q + 1] = fast_tanh(hi);
            }

        __syncthreads();   // all hd reads of step t complete
#pragma unroll
        for (int i = 0; i < 4; i++) {
            unsigned long long* hr = hd + (r0 + i) * H;
#pragma unroll
            for (int q = 0; q < 4; q += 2) {   // two dup-pairs per STS.128
                const int j = j0 + 2 * q;
                if (H == HP || j + 1 < H) {
                    ulonglong2 pr;
                    pr.x = pk2(out[i][2 * q],     out[i][2 * q]);
                    pr.y = pk2(out[i][2 * q + 1], out[i][2 * q + 1]);
                    *(ulonglong2*)&hr[j] = pr;
                }
                const int j2 = j0 + 2 * (q + 1);
                if (H == HP || j2 + 1 < H) {
                    ulonglong2 pr;
                    pr.x = pk2(out[i][2 * q + 2], out[i][2 * q + 2]);
                    pr.y = pk2(out[i][2 * q + 3], out[i][2 * q + 3]);
                    *(ulonglong2*)&hr[j2] = pr;
                }
                break;   // the two pairs above cover q=0..1; loop trick avoided:
            }
            // remaining two pairs (cols j0+4..j0+7)
            {
                const int j = j0 + 4;
                if (H == HP || j + 1 < H) {
                    ulonglong2 pr;
                    pr.x = pk2(out[i][4], out[i][4]);
                    pr.y = pk2(out[i][5], out[i][5]);
                    *(ulonglong2*)&hr[j] = pr;
                }
                const int j2 = j0 + 6;
                if (H == HP || j2 + 1 < H) {
                    ulonglong2 pr;
                    pr.x = pk2(out[i][6], out[i][6]);
                    pr.y = pk2(out[i][7], out[i][7]);
                    *(ulonglong2*)&hr[j2] = pr;
                }
            }
            float* yr = Yout + ((b0 + r0 + i) * T + t) * H + j0;
            if (H == HP) {
                *(float4*)yr       = make_float4(out[i][0], out[i][1], out[i][2], out[i][3]);
                *(float4*)(yr + 4) = make_float4(out[i][4], out[i][5], out[i][6], out[i][7]);
            } else {
                if (j0 + 4 <= H)
                    *(float4*)yr = make_float4(out[i][0], out[i][1], out[i][2], out[i][3]);
                if (j0 + 8 <= H)
                    *(float4*)(yr + 4) = make_float4(out[i][4], out[i][5], out[i][6], out[i][7]);
            }
        }
        __syncthreads();   // hd ready for step t+1

#pragma unroll
        for (int i = 0; i < 4; i++)
#pragma unroll
            for (int c = 0; c < 8; c++) xp[i][c] = xn[i][c];
    }
}

// ---------------- launch ----------------
extern "C" void kernel_launch(void* const* d_in, const int* in_sizes, int n_in,
                              void* d_out, int out_size)
{
    (void)in_sizes; (void)n_in; (void)out_size;
    const float* x    = (const float*)d_in[0];
    const float* wih0 = (const float*)d_in[1];
    const float* whh0 = (const float*)d_in[2];
    const float* bi0  = (const float*)d_in[3];
    const float* bh0  = (const float*)d_in[4];
    const float* wih1 = (const float*)d_in[5];
    const float* whh1 = (const float*)d_in[6];
    const float* bi1  = (const float*)d_in[7];
    const float* bh1  = (const float*)d_in[8];
    const float* wih2 = (const float*)d_in[9];
    const float* whh2 = (const float*)d_in[10];
    const float* bi2  = (const float*)d_in[11];
    const float* bh2  = (const float*)d_in[12];
    float* out = (float*)d_out;

    void* p;
    cudaGetSymbolAddress(&p, g_bufA);   float* bufA = (float*)p;
    cudaGetSymbolAddress(&p, g_bufB);   float* bufB = (float*)p;
    cudaGetSymbolAddress(&p, g_wih0t);  float* W0i  = (float*)p;
    cudaGetSymbolAddress(&p, g_whh0t);  float* W0h  = (float*)p;
    cudaGetSymbolAddress(&p, g_b0);     float* Bs0  = (float*)p;
    cudaGetSymbolAddress(&p, g_wih1t);  float* W1i  = (float*)p;
    cudaGetSymbolAddress(&p, g_whh1t);  float* W1h  = (float*)p;
    cudaGetSymbolAddress(&p, g_b1);     float* Bs1  = (float*)p;
    cudaGetSymbolAddress(&p, g_wih2t);  float* W2i  = (float*)p;
    cudaGetSymbolAddress(&p, g_whh2t);  float* W2h  = (float*)p;
    cudaGetSymbolAddress(&p, g_b2);     float* Bs2  = (float*)p;

    // smem: ws (K*NP floats) + xd (128*CH u64) + bs (NP floats)
    const int smem_p0 = (84  * 128) * 4 + 128 * 28 * 8 + 128 * 4;  // 72,192
    const int smem_p1 = (128 * 128) * 4 + 128 * 32 * 8 + 128 * 4;  // 98,816
    const int smem_p2 = (128 * 96 ) * 4 + 128 * 32 * 8 + 96  * 4;  // 82,304
    // smem: ws (H*HP floats) + hd (BB*H u64)
    const int smem_r1 = (128 * 128) * 4 + 32 * 128 * 8;            // 98,304
    const int smem_r2 = (84  * 96 ) * 4 + 32 * 84  * 8;            // 53,760

    cudaFuncSetAttribute((const void*)proj_kernel<84, 128, 128, 28, 256>,
                         cudaFuncAttributeMaxDynamicSharedMemorySize, smem_p0);
    cudaFuncSetAttribute((const void*)proj_kernel<128, 128, 128, 32, 256>,
                         cudaFuncAttributeMaxDynamicSharedMemorySize, smem_p1);
    cudaFuncSetAttribute((const void*)proj_kernel<128, 84, 96, 32, 192>,
                         cudaFuncAttributeMaxDynamicSharedMemorySize, smem_p2);
    cudaFuncSetAttribute((const void*)rnn_kernel<128, 128, 32>,
                         cudaFuncAttributeMaxDynamicSharedMemorySize, smem_r1);
    cudaFuncSetAttribute((const void*)rnn_kernel<84, 96, 32>,
                         cudaFuncAttributeMaxDynamicSharedMemorySize, smem_r2);

    prep_kernel<<<96, 256>>>(wih0, whh0, bi0, bh0,
                             wih1, whh1, bi1, bh1,
                             wih2, whh2, bi2, bh2);

    const int mblocks = (int)(M / 128);   // 4096
    const int rblocks = B / 32;           // 256

    // Layer 0: x (K=84) -> bufA, scan in-place
    proj_kernel<84, 128, 128, 28, 256><<<mblocks, 256, smem_p0>>>(x, W0i, Bs0, bufA);
    rnn_kernel<128, 128, 32><<<rblocks, 128, smem_r1>>>(bufA, W0h, bufA);

    // Layer 1: bufA -> bufB, scan in-place
    proj_kernel<128, 128, 128, 32, 256><<<mblocks, 256, smem_p1>>>(bufA, W1i, Bs1, bufB);
    rnn_kernel<128, 128, 32><<<rblocks, 128, smem_r1>>>(bufB, W1h, bufB);

    // Layer 2: bufB -> bufA (stride 84), scan writes final output
    proj_kernel<128, 84, 96, 32, 192><<<mblocks, 192, smem_p2>>>(bufB, W2i, Bs2, bufA);
    rnn_kernel<84, 96, 32><<<rblocks, 96, smem_r2>>>(bufA, W2h, out);
}

// round 7
// speedup vs baseline: 1.3886x; 1.3031x over previous
#include <cuda_runtime.h>

// ---------------------------------------------------------------------------
// 3-layer Elman RNN: (B=8192, T=64) 84 -> 128 -> 128 -> 84
// h_t = tanh(x_t W_ih^T + b_ih + b_hh + h_{t-1} W_hh^T)
//
// v4: - warp lanes span ROW-groups (ig fastest): weight LDS.128 now covers
//       64-128B/warp = 1 wavefront (was 512B = 4)
//     - broadcast operand (x / h) stored as ulonglong2 k-pairs with row
//       stride CSP == 1 (mod 8) and interleaved row assignment: lane
//       addresses differ by 16B mod 128 -> bank-spread, 16B-aligned
//     - both kernels now FFMA2-issue-bound instead of smem-crossbar-bound
// ---------------------------------------------------------------------------

namespace {
constexpr int B  = 8192;
constexpr int T  = 64;
constexpr int IN = 84;
constexpr int H1 = 128;
constexpr int H2 = 84;
constexpr long M = (long)B * T;   // 524288 rows
}

// Scratch ping-pong buffers (device globals: allocation-free rule)
__device__ float g_bufA[(size_t)M * H1];
__device__ float g_bufB[(size_t)M * H1];

// Pre-transposed / padded weights & fused biases
__device__ float g_wih0t[IN * H1];    // [k][n]
__device__ float g_whh0t[H1 * H1];
__device__ float g_b0[H1];
__device__ float g_wih1t[H1 * H1];
__device__ float g_whh1t[H1 * H1];
__device__ float g_b1[H1];
__device__ float g_wih2t[H1 * 96];    // n>=84 zero
__device__ float g_whh2t[IN * 96];    // j>=84 zero
__device__ float g_b2[96];

// ---------------- packed f32x2 helpers ----------------
__device__ __forceinline__ unsigned long long pk2(float lo, float hi) {
    unsigned long long r;
    asm("mov.b64 %0, {%1, %2};" : "=l"(r) : "f"(lo), "f"(hi));
    return r;
}
__device__ __forceinline__ void upk2(float& lo, float& hi, unsigned long long v) {
    asm("mov.b64 {%0, %1}, %2;" : "=f"(lo), "=f"(hi) : "l"(v));
}
__device__ __forceinline__ void fma2(unsigned long long& d, unsigned long long a,
                                     unsigned long long b) {
    asm("fma.rn.f32x2 %0, %1, %2, %0;" : "+l"(d) : "l"(a), "l"(b));
}

// tanh(x) = 1 - 2/(exp(2x)+1); ex2/rcp approx ~1e-6 rel err, saturates cleanly.
__device__ __forceinline__ float fast_tanh(float x) {
    float e, r;
    asm("ex2.approx.f32 %0, %1;" : "=f"(e) : "f"(x * 2.885390081777927f));
    asm("rcp.approx.f32 %0, %1;" : "=f"(r) : "f"(e + 1.0f));
    return fmaf(-2.0f, r, 1.0f);
}

// ---------------- weight prep (transpose + pad + bias fuse) ----------------
__global__ void prep_kernel(
    const float* __restrict__ wih0, const float* __restrict__ whh0,
    const float* __restrict__ bi0,  const float* __restrict__ bh0,
    const float* __restrict__ wih1, const float* __restrict__ whh1,
    const float* __restrict__ bi1,  const float* __restrict__ bh1,
    const float* __restrict__ wih2, const float* __restrict__ whh2,
    const float* __restrict__ bi2,  const float* __restrict__ bh2)
{
    int tid = blockIdx.x * blockDim.x + threadIdx.x;
    int nt  = gridDim.x * blockDim.x;
    for (int i = tid; i < IN * H1; i += nt) {
        int k = i / H1, n = i % H1;
        g_wih0t[i] = wih0[n * IN + k];
    }
    for (int i = tid; i < H1 * H1; i += nt) {
        int k = i / H1, n = i % H1;
        g_whh0t[i] = whh0[n * H1 + k];
        g_wih1t[i] = wih1[n * H1 + k];
        g_whh1t[i] = whh1[n * H1 + k];
    }
    for (int i = tid; i < H1 * 96; i += nt) {
        int k = i / 96, n = i % 96;
        g_wih2t[i] = (n < H2) ? wih2[n * H1 + k] : 0.f;
    }
    for (int i = tid; i < IN * 96; i += nt) {
        int k = i / 96, n = i % 96;
        g_whh2t[i] = (n < H2) ? whh2[n * H2 + k] : 0.f;
    }
    for (int i = tid; i < H1; i += nt) {
        g_b0[i] = bi0[i] + bh0[i];
        g_b1[i] = bi1[i] + bh1[i];
    }
    for (int i = tid; i < 96; i += nt)
        g_b2[i] = (i < H2) ? (bi2[i] + bh2[i]) : 0.f;
}

// ---------------- input projection GEMM ----------------
// Y[m,0..N) = X[m,0..K) @ Wt[K,NP] + bias. Block tile 128 rows x NP cols.
// X staged in K-chunks of CH as duplicated k-pairs: xd[row][kk] = ulonglong2
//   ({x[2kk],x[2kk]},{x[2kk+1],x[2kk+1]}).  Row stride CSP == 1 (mod 8).
// Thread map: ig = tid % 16 (row group), jg = tid / 16 (col group);
//   rows r = ig + i*16 (interleaved) -> warp h/x loads spread across banks,
//   warp weight loads cover few jg -> 1 wavefront.
template<int K, int N, int NP, int CH, int NTHR>
__global__ void __launch_bounds__(NTHR, 2)
proj_kernel(const float* __restrict__ X, const float* __restrict__ Wt,
            const float* __restrict__ bias, float* __restrict__ Y)
{
    constexpr int NCH = K / CH;
    constexpr int KP  = CH / 2;                       // k-pairs per chunk
    constexpr int CSP = ((KP + 7) / 8) * 8 + 1;       // padded row stride (pairs)
    constexpr int VEC = (CH % 8 == 0) ? 4 : 2;        // global load width
    constexpr int TOT = 128 * CH / VEC;               // vec loads per chunk
    constexpr int NLD = (TOT + NTHR - 1) / NTHR;

    extern __shared__ float sm[];
    float* ws = sm;                                     // [K][NP]
    ulonglong2* xd = (ulonglong2*)(ws + K * NP);        // [128][CSP]
    float* bs = (float*)(xd + 128 * CSP);               // [NP]

    const int tid = threadIdx.x;
    const size_t m0 = (size_t)blockIdx.x * 128;
    const float* Xg = X + m0 * K;

    // cooperative load: weights + bias
    for (int i = tid; i < K * NP / 4; i += NTHR)
        ((float4*)ws)[i] = ((const float4*)Wt)[i];
    for (int i = tid; i < NP; i += NTHR) bs[i] = bias[i];

    const int ig = tid % 16;          // row group (fast within warp)
    const int jg = tid / 16;          // col group
    const int j0 = jg * 8;

    float pf[NLD][VEC];
    // prefetch chunk 0
#pragma unroll
    for (int it = 0; it < NLD; it++) {
        int idx = tid + it * NTHR;
        if ((TOT % NTHR == 0) || idx < TOT) {
            int e   = idx * VEC;
            int row = e / CH, kc = e % CH;
            const float* p = Xg + (size_t)row * K + kc;
            if (VEC == 4) {
                float4 v = *(const float4*)p;
                pf[it][0] = v.x; pf[it][1] = v.y;
                pf[it][2] = v.z; pf[it][3] = v.w;
            } else {
                float2 v = *(const float2*)p;
                pf[it][0] = v.x; pf[it][1] = v.y;
            }
        }
    }

    __syncthreads();   // ws, bs visible

    unsigned long long acc[8][4];
#pragma unroll
    for (int q = 0; q < 4; q++) {
        unsigned long long bq = pk2(bs[j0 + 2 * q], bs[j0 + 2 * q + 1]);
#pragma unroll
        for (int i = 0; i < 8; i++) acc[i][q] = bq;
    }

    for (int c = 0; c < NCH; c++) {
        // store prefetched chunk as duplicated k-pairs
#pragma unroll
        for (int it = 0; it < NLD; it++) {
            int idx = tid + it * NTHR;
            if ((TOT % NTHR == 0) || idx < TOT) {
                int e   = idx * VEC;
                int row = e / CH, kc = e % CH;
                ulonglong2 u0;
                u0.x = pk2(pf[it][0], pf[it][0]);
                u0.y = pk2(pf[it][1], pf[it][1]);
                xd[row * CSP + kc / 2] = u0;
                if (VEC == 4) {
                    ulonglong2 u1;
                    u1.x = pk2(pf[it][2], pf[it][2]);
                    u1.y = pk2(pf[it][3], pf[it][3]);
                    xd[row * CSP + kc / 2 + 1] = u1;
                }
            }
        }
        __syncthreads();

        // prefetch next chunk (LDGs overlap compute below)
        if (c + 1 < NCH) {
#pragma unroll
            for (int it = 0; it < NLD; it++) {
                int idx = tid + it * NTHR;
                if ((TOT % NTHR == 0) || idx < TOT) {
                    int e   = idx * VEC;
                    int row = e / CH, kc = e % CH;
                    const float* p = Xg + (size_t)row * K + (c + 1) * CH + kc;
                    if (VEC == 4) {
                        float4 v = *(const float4*)p;
                        pf[it][0] = v.x; pf[it][1] = v.y;
                        pf[it][2] = v.z; pf[it][3] = v.w;
                    } else {
                        float2 v = *(const float2*)p;
                        pf[it][0] = v.x; pf[it][1] = v.y;
                    }
                }
            }
        }

        // compute this chunk
#pragma unroll 4
        for (int kk = 0; kk < KP; kk++) {
            const int k = c * CH + 2 * kk;
            const ulonglong2 wA = *(const ulonglong2*)&ws[k * NP + j0];
            const ulonglong2 wB = *(const ulonglong2*)&ws[k * NP + j0 + 4];
            const ulonglong2 wC = *(const ulonglong2*)&ws[(k + 1) * NP + j0];
            const ulonglong2 wD = *(const ulonglong2*)&ws[(k + 1) * NP + j0 + 4];
#pragma unroll
            for (int i = 0; i < 8; i++) {
                const ulonglong2 xv = xd[(ig + i * 16) * CSP + kk];
                fma2(acc[i][0], xv.x, wA.x);
                fma2(acc[i][1], xv.x, wA.y);
                fma2(acc[i][2], xv.x, wB.x);
                fma2(acc[i][3], xv.x, wB.y);
                fma2(acc[i][0], xv.y, wC.x);
                fma2(acc[i][1], xv.y, wC.y);
                fma2(acc[i][2], xv.y, wD.x);
                fma2(acc[i][3], xv.y, wD.y);
            }
        }
        if (c + 1 < NCH) __syncthreads();   // xd reads done before next store
    }

    // epilogue
#pragma unroll
    for (int i = 0; i < 8; i++) {
        const int r = ig + i * 16;
        float* yr = Y + (m0 + r) * N;
        float o[8];
#pragma unroll
        for (int q = 0; q < 4; q++) upk2(o[2 * q], o[2 * q + 1], acc[i][q]);
        if (N == NP) {
            *(float4*)&yr[j0]     = make_float4(o[0], o[1], o[2], o[3]);
            *(float4*)&yr[j0 + 4] = make_float4(o[4], o[5], o[6], o[7]);
        } else {
            if (j0 + 4 <= N)
                *(float4*)&yr[j0] = make_float4(o[0], o[1], o[2], o[3]);
            if (j0 + 8 <= N)
                *(float4*)&yr[j0 + 4] = make_float4(o[4], o[5], o[6], o[7]);
        }
    }
}

// ---------------- recurrence scan ----------------
// Block owns BB=32 batch rows for all T steps. W_hh in smem; h kept in smem
// as duplicated k-pairs hd[row][kk] (ulonglong2), row stride HS2 == 1 (mod 8).
// Thread map: ig = tid % 8 (row group), jg = tid / 8 (col group);
//   rows r = ig + i*8 -> warp h-loads hit 8 distinct banks (1 wavefront),
//   warp weight loads cover 4 jg = 128B (1 wavefront).
template<int H, int HP, int BB>
__global__ void __launch_bounds__((HP / 8) * (BB / 4), 2)
rnn_kernel(const float* __restrict__ XP, const float* __restrict__ Wt,
           float* __restrict__ Yout)
{
    constexpr int NTHR = (HP / 8) * (BB / 4);
    constexpr int RG   = BB / 4;                        // 8 row groups
    constexpr int HS2  = ((H / 2 + 7) / 8) * 8 + 1;     // padded row stride (pairs)

    extern __shared__ float sm[];
    float* ws = sm;                                     // [H][HP]
    ulonglong2* hd = (ulonglong2*)(ws + H * HP);        // [BB][HS2]

    const int tid = threadIdx.x;
    const size_t b0 = (size_t)blockIdx.x * BB;

    for (int i = tid; i < H * HP / 4; i += NTHR)
        ((float4*)ws)[i] = ((const float4*)Wt)[i];
    {
        ulonglong2 z; z.x = 0ull; z.y = 0ull;
        for (int i = tid; i < BB * HS2; i += NTHR) hd[i] = z;
    }
    __syncthreads();

    const int ig = tid % RG;
    const int jg = tid / RG;
    const int j0 = jg * 8;

    float xp[4][8];
#pragma unroll
    for (int i = 0; i < 4; i++) {
        const int r = ig + i * RG;
        const float* p = XP + ((b0 + r) * T + 0) * H + j0;
        float4 a = (j0 + 4 <= H) ? *(const float4*)p       : make_float4(0,0,0,0);
        float4 b = (j0 + 8 <= H) ? *(const float4*)(p + 4) : make_float4(0,0,0,0);
        xp[i][0]=a.x; xp[i][1]=a.y; xp[i][2]=a.z; xp[i][3]=a.w;
        xp[i][4]=b.x; xp[i][5]=b.y; xp[i][6]=b.z; xp[i][7]=b.w;
    }

    for (int t = 0; t < T; t++) {
        // prefetch next step's xp (overlaps the k-loop)
        float xn[4][8];
        if (t + 1 < T) {
#pragma unroll
            for (int i = 0; i < 4; i++) {
                const int r = ig + i * RG;
                const float* p = XP + ((b0 + r) * T + (t + 1)) * H + j0;
                float4 a = (j0 + 4 <= H) ? *(const float4*)p       : make_float4(0,0,0,0);
                float4 b = (j0 + 8 <= H) ? *(const float4*)(p + 4) : make_float4(0,0,0,0);
                xn[i][0]=a.x; xn[i][1]=a.y; xn[i][2]=a.z; xn[i][3]=a.w;
                xn[i][4]=b.x; xn[i][5]=b.y; xn[i][6]=b.z; xn[i][7]=b.w;
            }
        } else {
#pragma unroll
            for (int i = 0; i < 4; i++)
#pragma unroll
                for (int c = 0; c < 8; c++) xn[i][c] = 0.f;
        }

        unsigned long long acc[4][4];
#pragma unroll
        for (int i = 0; i < 4; i++)
#pragma unroll
            for (int q = 0; q < 4; q++)
                acc[i][q] = pk2(xp[i][2 * q], xp[i][2 * q + 1]);

#pragma unroll 4
        for (int kk = 0; kk < H / 2; kk++) {
            const int k = 2 * kk;
            const ulonglong2 wA = *(const ulonglong2*)&ws[k * HP + j0];
            const ulonglong2 wB = *(const ulonglong2*)&ws[k * HP + j0 + 4];
            const ulonglong2 wC = *(const ulonglong2*)&ws[(k + 1) * HP + j0];
            const ulonglong2 wD = *(const ulonglong2*)&ws[(k + 1) * HP + j0 + 4];
#pragma unroll
            for (int i = 0; i < 4; i++) {
                const ulonglong2 hv = hd[(ig + i * RG) * HS2 + kk];
                fma2(acc[i][0], hv.x, wA.x);
                fma2(acc[i][1], hv.x, wA.y);
                fma2(acc[i][2], hv.x, wB.x);
                fma2(acc[i][3], hv.x, wB.y);
                fma2(acc[i][0], hv.y, wC.x);
                fma2(acc[i][1], hv.y, wC.y);
                fma2(acc[i][2], hv.y, wD.x);
                fma2(acc[i][3], hv.y, wD.y);
            }
        }

        float out[4][8];
#pragma unroll
        for (int i = 0; i < 4; i++)
#pragma unroll
            for (int q = 0; q < 4; q++) {
                float lo, hi;
                upk2(lo, hi, acc[i][q]);
                out[i][2 * q]     = fast_tanh(lo);
                out[i][2 * q + 1] = fast_tanh(hi);
            }

        __syncthreads();   // all hd reads of step t complete
#pragma unroll
        for (int i = 0; i < 4; i++) {
            const int r = ig + i * RG;
            ulonglong2* hr = hd + r * HS2 + j0 / 2;
#pragma unroll
            for (int q = 0; q < 4; q++) {
                // always in-bounds (HS2 padded); cols >= H are never read
                ulonglong2 u;
                u.x = pk2(out[i][2 * q],     out[i][2 * q]);
                u.y = pk2(out[i][2 * q + 1], out[i][2 * q + 1]);
                hr[q] = u;
            }
            float* yr = Yout + ((b0 + r) * T + t) * H + j0;
            if (H == HP) {
                *(float4*)yr       = make_float4(out[i][0], out[i][1], out[i][2], out[i][3]);
                *(float4*)(yr + 4) = make_float4(out[i][4], out[i][5], out[i][6], out[i][7]);
            } else {
                if (j0 + 4 <= H)
                    *(float4*)yr = make_float4(out[i][0], out[i][1], out[i][2], out[i][3]);
                if (j0 + 8 <= H)
                    *(float4*)(yr + 4) = make_float4(out[i][4], out[i][5], out[i][6], out[i][7]);
            }
        }
        __syncthreads();   // hd ready for step t+1

#pragma unroll
        for (int i = 0; i < 4; i++)
#pragma unroll
            for (int c = 0; c < 8; c++) xp[i][c] = xn[i][c];
    }
}

// ---------------- launch ----------------
extern "C" void kernel_launch(void* const* d_in, const int* in_sizes, int n_in,
                              void* d_out, int out_size)
{
    (void)in_sizes; (void)n_in; (void)out_size;
    const float* x    = (const float*)d_in[0];
    const float* wih0 = (const float*)d_in[1];
    const float* whh0 = (const float*)d_in[2];
    const float* bi0  = (const float*)d_in[3];
    const float* bh0  = (const float*)d_in[4];
    const float* wih1 = (const float*)d_in[5];
    const float* whh1 = (const float*)d_in[6];
    const float* bi1  = (const float*)d_in[7];
    const float* bh1  = (const float*)d_in[8];
    const float* wih2 = (const float*)d_in[9];
    const float* whh2 = (const float*)d_in[10];
    const float* bi2  = (const float*)d_in[11];
    const float* bh2  = (const float*)d_in[12];
    float* out = (float*)d_out;

    void* p;
    cudaGetSymbolAddress(&p, g_bufA);   float* bufA = (float*)p;
    cudaGetSymbolAddress(&p, g_bufB);   float* bufB = (float*)p;
    cudaGetSymbolAddress(&p, g_wih0t);  float* W0i  = (float*)p;
    cudaGetSymbolAddress(&p, g_whh0t);  float* W0h  = (float*)p;
    cudaGetSymbolAddress(&p, g_b0);     float* Bs0  = (float*)p;
    cudaGetSymbolAddress(&p, g_wih1t);  float* W1i  = (float*)p;
    cudaGetSymbolAddress(&p, g_whh1t);  float* W1h  = (float*)p;
    cudaGetSymbolAddress(&p, g_b1);     float* Bs1  = (float*)p;
    cudaGetSymbolAddress(&p, g_wih2t);  float* W2i  = (float*)p;
    cudaGetSymbolAddress(&p, g_whh2t);  float* W2h  = (float*)p;
    cudaGetSymbolAddress(&p, g_b2);     float* Bs2  = (float*)p;

    // smem: ws (K*NP f32) + xd (128*CSP ulonglong2) + bs (NP f32)
    const int smem_p0 = 84  * 128 * 4 + 128 * 17 * 16 + 128 * 4;  // 78,336
    const int smem_p1 = 128 * 128 * 4 + 128 * 17 * 16 + 128 * 4;  // 100,864
    const int smem_p2 = 128 * 96  * 4 + 128 * 17 * 16 + 96  * 4;  // 84,352
    // smem: ws (H*HP f32) + hd (BB*HS2 ulonglong2)
    const int smem_r1 = 128 * 128 * 4 + 32 * 65 * 16;             // 98,816
    const int smem_r2 = 84  * 96  * 4 + 32 * 49 * 16;             // 57,344

    cudaFuncSetAttribute((const void*)proj_kernel<84, 128, 128, 28, 256>,
                         cudaFuncAttributeMaxDynamicSharedMemorySize, smem_p0);
    cudaFuncSetAttribute((const void*)proj_kernel<128, 128, 128, 32, 256>,
                         cudaFuncAttributeMaxDynamicSharedMemorySize, smem_p1);
    cudaFuncSetAttribute((const void*)proj_kernel<128, 84, 96, 32, 192>,
                         cudaFuncAttributeMaxDynamicSharedMemorySize, smem_p2);
    cudaFuncSetAttribute((const void*)rnn_kernel<128, 128, 32>,
                         cudaFuncAttributeMaxDynamicSharedMemorySize, smem_r1);
    cudaFuncSetAttribute((const void*)rnn_kernel<84, 96, 32>,
                         cudaFuncAttributeMaxDynamicSharedMemorySize, smem_r2);

    prep_kernel<<<96, 256>>>(wih0, whh0, bi0, bh0,
                             wih1, whh1, bi1, bh1,
                             wih2, whh2, bi2, bh2);

    const int mblocks = (int)(M / 128);   // 4096
    const int rblocks = B / 32;           // 256

    // Layer 0: x (K=84) -> bufA, scan in-place
    proj_kernel<84, 128, 128, 28, 256><<<mblocks, 256, smem_p0>>>(x, W0i, Bs0, bufA);
    rnn_kernel<128, 128, 32><<<rblocks, 128, smem_r1>>>(bufA, W0h, bufA);

    // Layer 1: bufA -> bufB, scan in-place
    proj_kernel<128, 128, 128, 32, 256><<<mblocks, 256, smem_p1>>>(bufA, W1i, Bs1, bufB);
    rnn_kernel<128, 128, 32><<<rblocks, 128, smem_r1>>>(bufB, W1h, bufB);

    // Layer 2: bufB -> bufA (stride 84), scan writes final output
    proj_kernel<128, 84, 96, 32, 192><<<mblocks, 192, smem_p2>>>(bufB, W2i, Bs2, bufA);
    rnn_kernel<84, 96, 32><<<rblocks, 96, smem_r2>>>(bufA, W2h, out);
}

// round 9
// speedup vs baseline: 1.6257x; 1.1708x over previous
#include <cuda_runtime.h>

// ---------------------------------------------------------------------------
// 3-layer Elman RNN: (B=8192, T=64) 84 -> 128 -> 128 -> 84
// h_t = tanh(x_t W_ih^T + b_ih + b_hh + h_{t-1} W_hh^T)
//
// v5: - proj thread tile 8x16 (CTA = NP threads): 128 FFMA2 per k-pair vs
//       16 shared-mem loads -> shared crossbar no longer binding
//     - x / h stored UNduplicated as float2 k-pairs (LDS.64, half the request
//       bytes); {v,v} operands built with mov.b64 on the alu pipe
//     - weights read as ulonglong2 (packed col-pairs), 2 k per iteration
// ---------------------------------------------------------------------------

namespace {
constexpr int B  = 8192;
constexpr int T  = 64;
constexpr int IN = 84;
constexpr int H1 = 128;
constexpr int H2 = 84;
constexpr long M = (long)B * T;   // 524288 rows
}

// Scratch ping-pong buffers (device globals: allocation-free rule)
__device__ float g_bufA[(size_t)M * H1];
__device__ float g_bufB[(size_t)M * H1];

// Pre-transposed / padded weights & fused biases
__device__ float g_wih0t[IN * H1];    // [k][n]
__device__ float g_whh0t[H1 * H1];
__device__ float g_b0[H1];
__device__ float g_wih1t[H1 * H1];
__device__ float g_whh1t[H1 * H1];
__device__ float g_b1[H1];
__device__ float g_wih2t[H1 * 96];    // n>=84 zero
__device__ float g_whh2t[IN * 96];    // j>=84 zero
__device__ float g_b2[96];

// ---------------- packed f32x2 helpers ----------------
__device__ __forceinline__ unsigned long long pk2(float lo, float hi) {
    unsigned long long r;
    asm("mov.b64 %0, {%1, %2};" : "=l"(r) : "f"(lo), "f"(hi));
    return r;
}
__device__ __forceinline__ void upk2(float& lo, float& hi, unsigned long long v) {
    asm("mov.b64 {%0, %1}, %2;" : "=f"(lo), "=f"(hi) : "l"(v));
}
__device__ __forceinline__ void fma2(unsigned long long& d, unsigned long long a,
                                     unsigned long long b) {
    asm("fma.rn.f32x2 %0, %1, %2, %0;" : "+l"(d) : "l"(a), "l"(b));
}

// tanh(x) = 1 - 2/(exp(2x)+1); ex2/rcp approx ~1e-6 rel err, saturates cleanly.
__device__ __forceinline__ float fast_tanh(float x) {
    float e, r;
    asm("ex2.approx.f32 %0, %1;" : "=f"(e) : "f"(x * 2.885390081777927f));
    asm("rcp.approx.f32 %0, %1;" : "=f"(r) : "f"(e + 1.0f));
    return fmaf(-2.0f, r, 1.0f);
}

// ---------------- weight prep (transpose + pad + bias fuse) ----------------
__global__ void prep_kernel(
    const float* __restrict__ wih0, const float* __restrict__ whh0,
    const float* __restrict__ bi0,  const float* __restrict__ bh0,
    const float* __restrict__ wih1, const float* __restrict__ whh1,
    const float* __restrict__ bi1,  const float* __restrict__ bh1,
    const float* __restrict__ wih2, const float* __restrict__ whh2,
    const float* __restrict__ bi2,  const float* __restrict__ bh2)
{
    int tid = blockIdx.x * blockDim.x + threadIdx.x;
    int nt  = gridDim.x * blockDim.x;
    for (int i = tid; i < IN * H1; i += nt) {
        int k = i / H1, n = i % H1;
        g_wih0t[i] = wih0[n * IN + k];
    }
    for (int i = tid; i < H1 * H1; i += nt) {
        int k = i / H1, n = i % H1;
        g_whh0t[i] = whh0[n * H1 + k];
        g_wih1t[i] = wih1[n * H1 + k];
        g_whh1t[i] = whh1[n * H1 + k];
    }
    for (int i = tid; i < H1 * 96; i += nt) {
        int k = i / 96, n = i % 96;
        g_wih2t[i] = (n < H2) ? wih2[n * H1 + k] : 0.f;
    }
    for (int i = tid; i < IN * 96; i += nt) {
        int k = i / 96, n = i % 96;
        g_whh2t[i] = (n < H2) ? whh2[n * H2 + k] : 0.f;
    }
    for (int i = tid; i < H1; i += nt) {
        g_b0[i] = bi0[i] + bh0[i];
        g_b1[i] = bi1[i] + bh1[i];
    }
    for (int i = tid; i < 96; i += nt)
        g_b2[i] = (i < H2) ? (bi2[i] + bh2[i]) : 0.f;
}

// ---------------- input projection GEMM ----------------
// Y[m,0..N) = X[m,0..K) @ Wt[K,NP] + bias. Block tile 128 rows x NP cols.
// Thread tile 8 rows x 16 cols; NTHR = NP threads. ig = tid%16, jg = tid/16.
// X staged per K-chunk as plain float2 k-pairs xs[row][kk] (stride CSP2 odd).
template<int K, int N, int NP, int CH, int NTHR>
__global__ void __launch_bounds__(NTHR, 2)
proj_kernel(const float* __restrict__ X, const float* __restrict__ Wt,
            const float* __restrict__ bias, float* __restrict__ Y)
{
    constexpr int NCH  = K / CH;
    constexpr int KP   = CH / 2;                      // k-pairs per chunk
    constexpr int CSP2 = (KP % 2 == 0) ? KP + 1 : KP; // odd stride (float2 units)
    constexpr int VEC  = (CH % 8 == 0) ? 4 : 2;       // global load width
    constexpr int TOT  = 128 * CH / VEC;              // vec loads per chunk
    constexpr int NLD  = (TOT + NTHR - 1) / NTHR;

    extern __shared__ float sm[];
    float*  ws = sm;                                  // [K][NP]
    float2* xs = (float2*)(ws + K * NP);              // [128][CSP2]
    float*  bs = (float*)(xs + 128 * CSP2);           // [NP]

    const int tid = threadIdx.x;
    const size_t m0 = (size_t)blockIdx.x * 128;
    const float* Xg = X + m0 * K;

    // cooperative load: weights + bias
    for (int i = tid; i < K * NP / 4; i += NTHR)
        ((float4*)ws)[i] = ((const float4*)Wt)[i];
    for (int i = tid; i < NP; i += NTHR) bs[i] = bias[i];

    const int ig = tid % 16;          // row group
    const int jg = tid / 16;          // col group (16 cols)
    const int j0 = jg * 16;

    float pf[NLD][VEC];
    // prefetch chunk 0
#pragma unroll
    for (int it = 0; it < NLD; it++) {
        int idx = tid + it * NTHR;
        if ((TOT % NTHR == 0) || idx < TOT) {
            int e   = idx * VEC;
            int row = e / CH, kc = e % CH;
            const float* p = Xg + (size_t)row * K + kc;
            if (VEC == 4) {
                float4 v = *(const float4*)p;
                pf[it][0] = v.x; pf[it][1] = v.y;
                pf[it][2] = v.z; pf[it][3] = v.w;
            } else {
                float2 v = *(const float2*)p;
                pf[it][0] = v.x; pf[it][1] = v.y;
            }
        }
    }

    __syncthreads();   // ws, bs visible

    unsigned long long acc[8][8];
#pragma unroll
    for (int q = 0; q < 8; q++) {
        unsigned long long bq = pk2(bs[j0 + 2 * q], bs[j0 + 2 * q + 1]);
#pragma unroll
        for (int i = 0; i < 8; i++) acc[i][q] = bq;
    }

    for (int c = 0; c < NCH; c++) {
        // store prefetched chunk as float2 k-pairs (no duplication)
#pragma unroll
        for (int it = 0; it < NLD; it++) {
            int idx = tid + it * NTHR;
            if ((TOT % NTHR == 0) || idx < TOT) {
                int e   = idx * VEC;
                int row = e / CH, kc = e % CH;
                xs[row * CSP2 + kc / 2]     = make_float2(pf[it][0], pf[it][1]);
                if (VEC == 4)
                    xs[row * CSP2 + kc / 2 + 1] = make_float2(pf[it][2], pf[it][3]);
            }
        }
        __syncthreads();

        // prefetch next chunk (LDGs overlap compute below)
        if (c + 1 < NCH) {
#pragma unroll
            for (int it = 0; it < NLD; it++) {
                int idx = tid + it * NTHR;
                if ((TOT % NTHR == 0) || idx < TOT) {
                    int e   = idx * VEC;
                    int row = e / CH, kc = e % CH;
                    const float* p = Xg + (size_t)row * K + (c + 1) * CH + kc;
                    if (VEC == 4) {
                        float4 v = *(const float4*)p;
                        pf[it][0] = v.x; pf[it][1] = v.y;
                        pf[it][2] = v.z; pf[it][3] = v.w;
                    } else {
                        float2 v = *(const float2*)p;
                        pf[it][0] = v.x; pf[it][1] = v.y;
                    }
                }
            }
        }

        // compute this chunk: per k-pair 8 weight LDS.128 + 8 x LDS.64,
        // 16 mov.b64, 128 FFMA2
#pragma unroll 2
        for (int kk = 0; kk < KP; kk++) {
            const int k = c * CH + 2 * kk;
            const ulonglong2 w0a = *(const ulonglong2*)&ws[k * NP + j0];
            const ulonglong2 w0b = *(const ulonglong2*)&ws[k * NP + j0 + 4];
            const ulonglong2 w0c = *(const ulonglong2*)&ws[k * NP + j0 + 8];
            const ulonglong2 w0d = *(const ulonglong2*)&ws[k * NP + j0 + 12];
            const ulonglong2 w1a = *(const ulonglong2*)&ws[(k + 1) * NP + j0];
            const ulonglong2 w1b = *(const ulonglong2*)&ws[(k + 1) * NP + j0 + 4];
            const ulonglong2 w1c = *(const ulonglong2*)&ws[(k + 1) * NP + j0 + 8];
            const ulonglong2 w1d = *(const ulonglong2*)&ws[(k + 1) * NP + j0 + 12];
#pragma unroll
            for (int i = 0; i < 8; i++) {
                const float2 xv = xs[(ig + i * 16) * CSP2 + kk];
                const unsigned long long a0 = pk2(xv.x, xv.x);
                const unsigned long long a1 = pk2(xv.y, xv.y);
                fma2(acc[i][0], a0, w0a.x);
                fma2(acc[i][1], a0, w0a.y);
                fma2(acc[i][2], a0, w0b.x);
                fma2(acc[i][3], a0, w0b.y);
                fma2(acc[i][4], a0, w0c.x);
                fma2(acc[i][5], a0, w0c.y);
                fma2(acc[i][6], a0, w0d.x);
                fma2(acc[i][7], a0, w0d.y);
                fma2(acc[i][0], a1, w1a.x);
                fma2(acc[i][1], a1, w1a.y);
                fma2(acc[i][2], a1, w1b.x);
                fma2(acc[i][3], a1, w1b.y);
                fma2(acc[i][4], a1, w1c.x);
                fma2(acc[i][5], a1, w1c.y);
                fma2(acc[i][6], a1, w1d.x);
                fma2(acc[i][7], a1, w1d.y);
            }
        }
        if (c + 1 < NCH) __syncthreads();   // xs reads done before next store
    }

    // epilogue: 16 cols per thread
#pragma unroll
    for (int i = 0; i < 8; i++) {
        const int r = ig + i * 16;
        float* yr = Y + (m0 + r) * N;
        float o[16];
#pragma unroll
        for (int q = 0; q < 8; q++) upk2(o[2 * q], o[2 * q + 1], acc[i][q]);
#pragma unroll
        for (int v = 0; v < 4; v++) {
            const int n = j0 + 4 * v;
            if (N == NP || n + 4 <= N)
                *(float4*)&yr[n] = make_float4(o[4*v], o[4*v+1], o[4*v+2], o[4*v+3]);
        }
    }
}

// ---------------- recurrence scan ----------------
// Block owns BB=32 batch rows for all T steps. W_hh in smem; h kept in smem
// as plain float2 k-pairs hs[row][kk] (stride HS2 odd). {v,v} via mov.b64.
template<int H, int HP, int BB>
__global__ void __launch_bounds__((HP / 8) * (BB / 4), 2)
rnn_kernel(const float* __restrict__ XP, const float* __restrict__ Wt,
           float* __restrict__ Yout)
{
    constexpr int NTHR = (HP / 8) * (BB / 4);
    constexpr int RG   = BB / 4;                          // 8 row groups
    constexpr int KPH  = H / 2;                           // k-pairs
    constexpr int HS2  = (KPH % 2 == 0) ? KPH + 1 : KPH;  // odd stride (float2)

    extern __shared__ float sm[];
    float*  ws = sm;                                      // [H][HP]
    float2* hs = (float2*)(ws + H * HP);                  // [BB][HS2]

    const int tid = threadIdx.x;
    const size_t b0 = (size_t)blockIdx.x * BB;

    for (int i = tid; i < H * HP / 4; i += NTHR)
        ((float4*)ws)[i] = ((const float4*)Wt)[i];
    for (int i = tid; i < BB * HS2; i += NTHR) hs[i] = make_float2(0.f, 0.f);
    __syncthreads();

    const int ig = tid % RG;
    const int jg = tid / RG;
    const int j0 = jg * 8;

    float xp[4][8];
#pragma unroll
    for (int i = 0; i < 4; i++) {
        const int r = ig + i * RG;
        const float* p = XP + ((b0 + r) * T + 0) * H + j0;
        float4 a = (j0 + 4 <= H) ? *(const float4*)p       : make_float4(0,0,0,0);
        float4 b = (j0 + 8 <= H) ? *(const float4*)(p + 4) : make_float4(0,0,0,0);
        xp[i][0]=a.x; xp[i][1]=a.y; xp[i][2]=a.z; xp[i][3]=a.w;
        xp[i][4]=b.x; xp[i][5]=b.y; xp[i][6]=b.z; xp[i][7]=b.w;
    }

    for (int t = 0; t < T; t++) {
        // prefetch next step's xp (overlaps the k-loop)
        float xn[4][8];
        if (t + 1 < T) {
#pragma unroll
            for (int i = 0; i < 4; i++) {
                const int r = ig + i * RG;
                const float* p = XP + ((b0 + r) * T + (t + 1)) * H + j0;
                float4 a = (j0 + 4 <= H) ? *(const float4*)p       : make_float4(0,0,0,0);
                float4 b = (j0 + 8 <= H) ? *(const float4*)(p + 4) : make_float4(0,0,0,0);
                xn[i][0]=a.x; xn[i][1]=a.y; xn[i][2]=a.z; xn[i][3]=a.w;
                xn[i][4]=b.x; xn[i][5]=b.y; xn[i][6]=b.z; xn[i][7]=b.w;
            }
        } else {
#pragma unroll
            for (int i = 0; i < 4; i++)
#pragma unroll
                for (int c = 0; c < 8; c++) xn[i][c] = 0.f;
        }

        unsigned long long acc[4][4];
#pragma unroll
        for (int i = 0; i < 4; i++)
#pragma unroll
            for (int q = 0; q < 4; q++)
                acc[i][q] = pk2(xp[i][2 * q], xp[i][2 * q + 1]);

#pragma unroll 4
        for (int kk = 0; kk < KPH; kk++) {
            const int k = 2 * kk;
            const ulonglong2 wA = *(const ulonglong2*)&ws[k * HP + j0];
            const ulonglong2 wB = *(const ulonglong2*)&ws[k * HP + j0 + 4];
            const ulonglong2 wC = *(const ulonglong2*)&ws[(k + 1) * HP + j0];
            const ulonglong2 wD = *(const ulonglong2*)&ws[(k + 1) * HP + j0 + 4];
#pragma unroll
            for (int i = 0; i < 4; i++) {
                const float2 hv = hs[(ig + i * RG) * HS2 + kk];
                const unsigned long long a0 = pk2(hv.x, hv.x);
                const unsigned long long a1 = pk2(hv.y, hv.y);
                fma2(acc[i][0], a0, wA.x);
                fma2(acc[i][1], a0, wA.y);
                fma2(acc[i][2], a0, wB.x);
                fma2(acc[i][3], a0, wB.y);
                fma2(acc[i][0], a1, wC.x);
                fma2(acc[i][1], a1, wC.y);
                fma2(acc[i][2], a1, wD.x);
                fma2(acc[i][3], a1, wD.y);
            }
        }

        float out[4][8];
#pragma unroll
        for (int i = 0; i < 4; i++)
#pragma unroll
            for (int q = 0; q < 4; q++) {
                float lo, hi;
                upk2(lo, hi, acc[i][q]);
                out[i][2 * q]     = fast_tanh(lo);
                out[i][2 * q + 1] = fast_tanh(hi);
            }

        __syncthreads();   // all hs reads of step t complete
#pragma unroll
        for (int i = 0; i < 4; i++) {
            const int r = ig + i * RG;
            float2* hr = hs + r * HS2 + j0 / 2;
#pragma unroll
            for (int q = 0; q < 4; q++) {
                // pair index p = j0/2 + q covers cols {2p, 2p+1}
                if (H == HP || j0 + 2 * q + 1 < H)
                    hr[q] = make_float2(out[i][2 * q], out[i][2 * q + 1]);
            }
            float* yr = Yout + ((b0 + r) * T + t) * H + j0;
            if (H == HP) {
                *(float4*)yr       = make_float4(out[i][0], out[i][1], out[i][2], out[i][3]);
                *(float4*)(yr + 4) = make_float4(out[i][4], out[i][5], out[i][6], out[i][7]);
            } else {
                if (j0 + 4 <= H)
                    *(float4*)yr = make_float4(out[i][0], out[i][1], out[i][2], out[i][3]);
                if (j0 + 8 <= H)
                    *(float4*)(yr + 4) = make_float4(out[i][4], out[i][5], out[i][6], out[i][7]);
            }
        }
        __syncthreads();   // hs ready for step t+1

#pragma unroll
        for (int i = 0; i < 4; i++)
#pragma unroll
            for (int c = 0; c < 8; c++) xp[i][c] = xn[i][c];
    }
}

// ---------------- launch ----------------
extern "C" void kernel_launch(void* const* d_in, const int* in_sizes, int n_in,
                              void* d_out, int out_size)
{
    (void)in_sizes; (void)n_in; (void)out_size;
    const float* x    = (const float*)d_in[0];
    const float* wih0 = (const float*)d_in[1];
    const float* whh0 = (const float*)d_in[2];
    const float* bi0  = (const float*)d_in[3];
    const float* bh0  = (const float*)d_in[4];
    const float* wih1 = (const float*)d_in[5];
    const float* whh1 = (const float*)d_in[6];
    const float* bi1  = (const float*)d_in[7];
    const float* bh1  = (const float*)d_in[8];
    const float* wih2 = (const float*)d_in[9];
    const float* whh2 = (const float*)d_in[10];
    const float* bi2  = (const float*)d_in[11];
    const float* bh2  = (const float*)d_in[12];
    float* out = (float*)d_out;

    void* p;
    cudaGetSymbolAddress(&p, g_bufA);   float* bufA = (float*)p;
    cudaGetSymbolAddress(&p, g_bufB);   float* bufB = (float*)p;
    cudaGetSymbolAddress(&p, g_wih0t);  float* W0i  = (float*)p;
    cudaGetSymbolAddress(&p, g_whh0t);  float* W0h  = (float*)p;
    cudaGetSymbolAddress(&p, g_b0);     float* Bs0  = (float*)p;
    cudaGetSymbolAddress(&p, g_wih1t);  float* W1i  = (float*)p;
    cudaGetSymbolAddress(&p, g_whh1t);  float* W1h  = (float*)p;
    cudaGetSymbolAddress(&p, g_b1);     float* Bs1  = (float*)p;
    cudaGetSymbolAddress(&p, g_wih2t);  float* W2i  = (float*)p;
    cudaGetSymbolAddress(&p, g_whh2t);  float* W2h  = (float*)p;
    cudaGetSymbolAddress(&p, g_b2);     float* Bs2  = (float*)p;

    // smem: ws (K*NP f32) + xs (128*CSP2 float2) + bs (NP f32)
    const int smem_p0 = 84  * 128 * 4 + 128 * 15 * 8 + 128 * 4;  // 58,880
    const int smem_p1 = 128 * 128 * 4 + 128 * 17 * 8 + 128 * 4;  // 83,456
    const int smem_p2 = 128 * 96  * 4 + 128 * 17 * 8 + 96  * 4;  // 66,944
    // smem: ws (H*HP f32) + hs (BB*HS2 float2)
    const int smem_r1 = 128 * 128 * 4 + 32 * 65 * 8;             // 82,176
    const int smem_r2 = 84  * 96  * 4 + 32 * 43 * 8;             // 43,264

    cudaFuncSetAttribute((const void*)proj_kernel<84, 128, 128, 28, 128>,
                         cudaFuncAttributeMaxDynamicSharedMemorySize, smem_p0);
    cudaFuncSetAttribute((const void*)proj_kernel<128, 128, 128, 32, 128>,
                         cudaFuncAttributeMaxDynamicSharedMemorySize, smem_p1);
    cudaFuncSetAttribute((const void*)proj_kernel<128, 84, 96, 32, 96>,
                         cudaFuncAttributeMaxDynamicSharedMemorySize, smem_p2);
    cudaFuncSetAttribute((const void*)rnn_kernel<128, 128, 32>,
                         cudaFuncAttributeMaxDynamicSharedMemorySize, smem_r1);
    cudaFuncSetAttribute((const void*)rnn_kernel<84, 96, 32>,
                         cudaFuncAttributeMaxDynamicSharedMemorySize, smem_r2);

    prep_kernel<<<96, 256>>>(wih0, whh0, bi0, bh0,
                             wih1, whh1, bi1, bh1,
                             wih2, whh2, bi2, bh2);

    const int mblocks = (int)(M / 128);   // 4096
    const int rblocks = B / 32;           // 256

    // Layer 0: x (K=84) -> bufA, scan in-place
    proj_kernel<84, 128, 128, 28, 128><<<mblocks, 128, smem_p0>>>(x, W0i, Bs0, bufA);
    rnn_kernel<128, 128, 32><<<rblocks, 128, smem_r1>>>(bufA, W0h, bufA);

    // Layer 1: bufA -> bufB, scan in-place
    proj_kernel<128, 128, 128, 32, 128><<<mblocks, 128, smem_p1>>>(bufA, W1i, Bs1, bufB);
    rnn_kernel<128, 128, 32><<<rblocks, 128, smem_r1>>>(bufB, W1h, bufB);

    // Layer 2: bufB -> bufA (stride 84), scan writes final output
    proj_kernel<128, 84, 96, 32, 96><<<mblocks, 96, smem_p2>>>(bufB, W2i, Bs2, bufA);
    rnn_kernel<84, 96, 32><<<rblocks, 96, smem_r2>>>(bufA, W2h, out);
}

// round 12
// speedup vs baseline: 1.6267x; 1.0006x over previous
#include <cuda_runtime.h>

// ---------------------------------------------------------------------------
// 3-layer Elman RNN: (B=8192, T=64) 84 -> 128 -> 128 -> 84
// h_t = tanh(x_t W_ih^T + b_ih + b_hh + h_{t-1} W_hh^T)
//
// v5: - proj thread tile 8x16 (CTA = NP threads): 128 FFMA2 per k-pair vs
//       16 shared-mem loads -> shared crossbar no longer binding
//     - x / h stored UNduplicated as float2 k-pairs (LDS.64, half the request
//       bytes); {v,v} operands built with mov.b64 on the alu pipe
//     - weights read as ulonglong2 (packed col-pairs), 2 k per iteration
// ---------------------------------------------------------------------------

namespace {
constexpr int B  = 8192;
constexpr int T  = 64;
constexpr int IN = 84;
constexpr int H1 = 128;
constexpr int H2 = 84;
constexpr long M = (long)B * T;   // 524288 rows
}

// Scratch ping-pong buffers (device globals: allocation-free rule)
__device__ float g_bufA[(size_t)M * H1];
__device__ float g_bufB[(size_t)M * H1];

// Pre-transposed / padded weights & fused biases
__device__ float g_wih0t[IN * H1];    // [k][n]
__device__ float g_whh0t[H1 * H1];
__device__ float g_b0[H1];
__device__ float g_wih1t[H1 * H1];
__device__ float g_whh1t[H1 * H1];
__device__ float g_b1[H1];
__device__ float g_wih2t[H1 * 96];    // n>=84 zero
__device__ float g_whh2t[IN * 96];    // j>=84 zero
__device__ float g_b2[96];

// ---------------- packed f32x2 helpers ----------------
__device__ __forceinline__ unsigned long long pk2(float lo, float hi) {
    unsigned long long r;
    asm("mov.b64 %0, {%1, %2};" : "=l"(r) : "f"(lo), "f"(hi));
    return r;
}
__device__ __forceinline__ void upk2(float& lo, float& hi, unsigned long long v) {
    asm("mov.b64 {%0, %1}, %2;" : "=f"(lo), "=f"(hi) : "l"(v));
}
__device__ __forceinline__ void fma2(unsigned long long& d, unsigned long long a,
                                     unsigned long long b) {
    asm("fma.rn.f32x2 %0, %1, %2, %0;" : "+l"(d) : "l"(a), "l"(b));
}

// tanh(x) = 1 - 2/(exp(2x)+1); ex2/rcp approx ~1e-6 rel err, saturates cleanly.
__device__ __forceinline__ float fast_tanh(float x) {
    float e, r;
    asm("ex2.approx.f32 %0, %1;" : "=f"(e) : "f"(x * 2.885390081777927f));
    asm("rcp.approx.f32 %0, %1;" : "=f"(r) : "f"(e + 1.0f));
    return fmaf(-2.0f, r, 1.0f);
}

// ---------------- weight prep (transpose + pad + bias fuse) ----------------
__global__ void prep_kernel(
    const float* __restrict__ wih0, const float* __restrict__ whh0,
    const float* __restrict__ bi0,  const float* __restrict__ bh0,
    const float* __restrict__ wih1, const float* __restrict__ whh1,
    const float* __restrict__ bi1,  const float* __restrict__ bh1,
    const float* __restrict__ wih2, const float* __restrict__ whh2,
    const float* __restrict__ bi2,  const float* __restrict__ bh2)
{
    int tid = blockIdx.x * blockDim.x + threadIdx.x;
    int nt  = gridDim.x * blockDim.x;
    for (int i = tid; i < IN * H1; i += nt) {
        int k = i / H1, n = i % H1;
        g_wih0t[i] = wih0[n * IN + k];
    }
    for (int i = tid; i < H1 * H1; i += nt) {
        int k = i / H1, n = i % H1;
        g_whh0t[i] = whh0[n * H1 + k];
        g_wih1t[i] = wih1[n * H1 + k];
        g_whh1t[i] = whh1[n * H1 + k];
    }
    for (int i = tid; i < H1 * 96; i += nt) {
        int k = i / 96, n = i % 96;
        g_wih2t[i] = (n < H2) ? wih2[n * H1 + k] : 0.f;
    }
    for (int i = tid; i < IN * 96; i += nt) {
        int k = i / 96, n = i % 96;
        g_whh2t[i] = (n < H2) ? whh2[n * H2 + k] : 0.f;
    }
    for (int i = tid; i < H1; i += nt) {
        g_b0[i] = bi0[i] + bh0[i];
        g_b1[i] = bi1[i] + bh1[i];
    }
    for (int i = tid; i < 96; i += nt)
        g_b2[i] = (i < H2) ? (bi2[i] + bh2[i]) : 0.f;
}

// ---------------- input projection GEMM ----------------
// Y[m,0..N) = X[m,0..K) @ Wt[K,NP] + bias. Block tile 128 rows x NP cols.
// Thread tile 8 rows x 16 cols; NTHR = NP threads. ig = tid%16, jg = tid/16.
// X staged per K-chunk as plain float2 k-pairs xs[row][kk] (stride CSP2 odd).
template<int K, int N, int NP, int CH, int NTHR>
__global__ void __launch_bounds__(NTHR, 2)
proj_kernel(const float* __restrict__ X, const float* __restrict__ Wt,
            const float* __restrict__ bias, float* __restrict__ Y)
{
    constexpr int NCH  = K / CH;
    constexpr int KP   = CH / 2;                      // k-pairs per chunk
    constexpr int CSP2 = (KP % 2 == 0) ? KP + 1 : KP; // odd stride (float2 units)
    constexpr int VEC  = (CH % 8 == 0) ? 4 : 2;       // global load width
    constexpr int TOT  = 128 * CH / VEC;              // vec loads per chunk
    constexpr int NLD  = (TOT + NTHR - 1) / NTHR;

    extern __shared__ float sm[];
    float*  ws = sm;                                  // [K][NP]
    float2* xs = (float2*)(ws + K * NP);              // [128][CSP2]
    float*  bs = (float*)(xs + 128 * CSP2);           // [NP]

    const int tid = threadIdx.x;
    const size_t m0 = (size_t)blockIdx.x * 128;
    const float* Xg = X + m0 * K;

    // cooperative load: weights + bias
    for (int i = tid; i < K * NP / 4; i += NTHR)
        ((float4*)ws)[i] = ((const float4*)Wt)[i];
    for (int i = tid; i < NP; i += NTHR) bs[i] = bias[i];

    const int ig = tid % 16;          // row group
    const int jg = tid / 16;          // col group (16 cols)
    const int j0 = jg * 16;

    float pf[NLD][VEC];
    // prefetch chunk 0
#pragma unroll
    for (int it = 0; it < NLD; it++) {
        int idx = tid + it * NTHR;
        if ((TOT % NTHR == 0) || idx < TOT) {
            int e   = idx * VEC;
            int row = e / CH, kc = e % CH;
            const float* p = Xg + (size_t)row * K + kc;
            if (VEC == 4) {
                float4 v = *(const float4*)p;
                pf[it][0] = v.x; pf[it][1] = v.y;
                pf[it][2] = v.z; pf[it][3] = v.w;
            } else {
                float2 v = *(const float2*)p;
                pf[it][0] = v.x; pf[it][1] = v.y;
            }
        }
    }

    __syncthreads();   // ws, bs visible

    unsigned long long acc[8][8];
#pragma unroll
    for (int q = 0; q < 8; q++) {
        unsigned long long bq = pk2(bs[j0 + 2 * q], bs[j0 + 2 * q + 1]);
#pragma unroll
        for (int i = 0; i < 8; i++) acc[i][q] = bq;
    }

    for (int c = 0; c < NCH; c++) {
        // store prefetched chunk as float2 k-pairs (no duplication)
#pragma unroll
        for (int it = 0; it < NLD; it++) {
            int idx = tid + it * NTHR;
            if ((TOT % NTHR == 0) || idx < TOT) {
                int e   = idx * VEC;
                int row = e / CH, kc = e % CH;
                xs[row * CSP2 + kc / 2]     = make_float2(pf[it][0], pf[it][1]);
                if (VEC == 4)
                    xs[row * CSP2 + kc / 2 + 1] = make_float2(pf[it][2], pf[it][3]);
            }
        }
        __syncthreads();

        // prefetch next chunk (LDGs overlap compute below)
        if (c + 1 < NCH) {
#pragma unroll
            for (int it = 0; it < NLD; it++) {
                int idx = tid + it * NTHR;
                if ((TOT % NTHR == 0) || idx < TOT) {
                    int e   = idx * VEC;
                    int row = e / CH, kc = e % CH;
                    const float* p = Xg + (size_t)row * K + (c + 1) * CH + kc;
                    if (VEC == 4) {
                        float4 v = *(const float4*)p;
                        pf[it][0] = v.x; pf[it][1] = v.y;
                        pf[it][2] = v.z; pf[it][3] = v.w;
                    } else {
                        float2 v = *(const float2*)p;
                        pf[it][0] = v.x; pf[it][1] = v.y;
                    }
                }
            }
        }

        // compute this chunk: per k-pair 8 weight LDS.128 + 8 x LDS.64,
        // 16 mov.b64, 128 FFMA2
#pragma unroll 2
        for (int kk = 0; kk < KP; kk++) {
            const int k = c * CH + 2 * kk;
            const ulonglong2 w0a = *(const ulonglong2*)&ws[k * NP + j0];
            const ulonglong2 w0b = *(const ulonglong2*)&ws[k * NP + j0 + 4];
            const ulonglong2 w0c = *(const ulonglong2*)&ws[k * NP + j0 + 8];
            const ulonglong2 w0d = *(const ulonglong2*)&ws[k * NP + j0 + 12];
            const ulonglong2 w1a = *(const ulonglong2*)&ws[(k + 1) * NP + j0];
            const ulonglong2 w1b = *(const ulonglong2*)&ws[(k + 1) * NP + j0 + 4];
            const ulonglong2 w1c = *(const ulonglong2*)&ws[(k + 1) * NP + j0 + 8];
            const ulonglong2 w1d = *(const ulonglong2*)&ws[(k + 1) * NP + j0 + 12];
#pragma unroll
            for (int i = 0; i < 8; i++) {
                const float2 xv = xs[(ig + i * 16) * CSP2 + kk];
                const unsigned long long a0 = pk2(xv.x, xv.x);
                const unsigned long long a1 = pk2(xv.y, xv.y);
                fma2(acc[i][0], a0, w0a.x);
                fma2(acc[i][1], a0, w0a.y);
                fma2(acc[i][2], a0, w0b.x);
                fma2(acc[i][3], a0, w0b.y);
                fma2(acc[i][4], a0, w0c.x);
                fma2(acc[i][5], a0, w0c.y);
                fma2(acc[i][6], a0, w0d.x);
                fma2(acc[i][7], a0, w0d.y);
                fma2(acc[i][0], a1, w1a.x);
                fma2(acc[i][1], a1, w1a.y);
                fma2(acc[i][2], a1, w1b.x);
                fma2(acc[i][3], a1, w1b.y);
                fma2(acc[i][4], a1, w1c.x);
                fma2(acc[i][5], a1, w1c.y);
                fma2(acc[i][6], a1, w1d.x);
                fma2(acc[i][7], a1, w1d.y);
            }
        }
        if (c + 1 < NCH) __syncthreads();   // xs reads done before next store
    }

    // epilogue: 16 cols per thread
#pragma unroll
    for (int i = 0; i < 8; i++) {
        const int r = ig + i * 16;
        float* yr = Y + (m0 + r) * N;
        float o[16];
#pragma unroll
        for (int q = 0; q < 8; q++) upk2(o[2 * q], o[2 * q + 1], acc[i][q]);
#pragma unroll
        for (int v = 0; v < 4; v++) {
            const int n = j0 + 4 * v;
            if (N == NP || n + 4 <= N)
                *(float4*)&yr[n] = make_float4(o[4*v], o[4*v+1], o[4*v+2], o[4*v+3]);
        }
    }
}

// ---------------- recurrence scan ----------------
// Block owns BB=32 batch rows for all T steps. W_hh in smem; h kept in smem
// as plain float2 k-pairs hs[row][kk] (stride HS2 odd). {v,v} via mov.b64.
template<int H, int HP, int BB>
__global__ void __launch_bounds__((HP / 8) * (BB / 4), 2)
rnn_kernel(const float* __restrict__ XP, const float* __restrict__ Wt,
           float* __restrict__ Yout)
{
    constexpr int NTHR = (HP / 8) * (BB / 4);
    constexpr int RG   = BB / 4;                          // 8 row groups
    constexpr int KPH  = H / 2;                           // k-pairs
    constexpr int HS2  = (KPH % 2 == 0) ? KPH + 1 : KPH;  // odd stride (float2)

    extern __shared__ float sm[];
    float*  ws = sm;                                      // [H][HP]
    float2* hs = (float2*)(ws + H * HP);                  // [BB][HS2]

    const int tid = threadIdx.x;
    const size_t b0 = (size_t)blockIdx.x * BB;

    for (int i = tid; i < H * HP / 4; i += NTHR)
        ((float4*)ws)[i] = ((const float4*)Wt)[i];
    for (int i = tid; i < BB * HS2; i += NTHR) hs[i] = make_float2(0.f, 0.f);
    __syncthreads();

    const int ig = tid % RG;
    const int jg = tid / RG;
    const int j0 = jg * 8;

    float xp[4][8];
#pragma unroll
    for (int i = 0; i < 4; i++) {
        const int r = ig + i * RG;
        const float* p = XP + ((b0 + r) * T + 0) * H + j0;
        float4 a = (j0 + 4 <= H) ? *(const float4*)p       : make_float4(0,0,0,0);
        float4 b = (j0 + 8 <= H) ? *(const float4*)(p + 4) : make_float4(0,0,0,0);
        xp[i][0]=a.x; xp[i][1]=a.y; xp[i][2]=a.z; xp[i][3]=a.w;
        xp[i][4]=b.x; xp[i][5]=b.y; xp[i][6]=b.z; xp[i][7]=b.w;
    }

    for (int t = 0; t < T; t++) {
        // prefetch next step's xp (overlaps the k-loop)
        float xn[4][8];
        if (t + 1 < T) {
#pragma unroll
            for (int i = 0; i < 4; i++) {
                const int r = ig + i * RG;
                const float* p = XP + ((b0 + r) * T + (t + 1)) * H + j0;
                float4 a = (j0 + 4 <= H) ? *(const float4*)p       : make_float4(0,0,0,0);
                float4 b = (j0 + 8 <= H) ? *(const float4*)(p + 4) : make_float4(0,0,0,0);
                xn[i][0]=a.x; xn[i][1]=a.y; xn[i][2]=a.z; xn[i][3]=a.w;
                xn[i][4]=b.x; xn[i][5]=b.y; xn[i][6]=b.z; xn[i][7]=b.w;
            }
        } else {
#pragma unroll
            for (int i = 0; i < 4; i++)
#pragma unroll
                for (int c = 0; c < 8; c++) xn[i][c] = 0.f;
        }

        unsigned long long acc[4][4];
#pragma unroll
        for (int i = 0; i < 4; i++)
#pragma unroll
            for (int q = 0; q < 4; q++)
                acc[i][q] = pk2(xp[i][2 * q], xp[i][2 * q + 1]);

#pragma unroll 4
        for (int kk = 0; kk < KPH; kk++) {
            const int k = 2 * kk;
            const ulonglong2 wA = *(const ulonglong2*)&ws[k * HP + j0];
            const ulonglong2 wB = *(const ulonglong2*)&ws[k * HP + j0 + 4];
            const ulonglong2 wC = *(const ulonglong2*)&ws[(k + 1) * HP + j0];
            const ulonglong2 wD = *(const ulonglong2*)&ws[(k + 1) * HP + j0 + 4];
#pragma unroll
            for (int i = 0; i < 4; i++) {
                const float2 hv = hs[(ig + i * RG) * HS2 + kk];
                const unsigned long long a0 = pk2(hv.x, hv.x);
                const unsigned long long a1 = pk2(hv.y, hv.y);
                fma2(acc[i][0], a0, wA.x);
                fma2(acc[i][1], a0, wA.y);
                fma2(acc[i][2], a0, wB.x);
                fma2(acc[i][3], a0, wB.y);
                fma2(acc[i][0], a1, wC.x);
                fma2(acc[i][1], a1, wC.y);
                fma2(acc[i][2], a1, wD.x);
                fma2(acc[i][3], a1, wD.y);
            }
        }

        float out[4][8];
#pragma unroll
        for (int i = 0; i < 4; i++)
#pragma unroll
            for (int q = 0; q < 4; q++) {
                float lo, hi;
                upk2(lo, hi, acc[i][q]);
                out[i][2 * q]     = fast_tanh(lo);
                out[i][2 * q + 1] = fast_tanh(hi);
            }

        __syncthreads();   // all hs reads of step t complete
#pragma unroll
        for (int i = 0; i < 4; i++) {
            const int r = ig + i * RG;
            float2* hr = hs + r * HS2 + j0 / 2;
#pragma unroll
            for (int q = 0; q < 4; q++) {
                // pair index p = j0/2 + q covers cols {2p, 2p+1}
                if (H == HP || j0 + 2 * q + 1 < H)
                    hr[q] = make_float2(out[i][2 * q], out[i][2 * q + 1]);
            }
            float* yr = Yout + ((b0 + r) * T + t) * H + j0;
            if (H == HP) {
                *(float4*)yr       = make_float4(out[i][0], out[i][1], out[i][2], out[i][3]);
                *(float4*)(yr + 4) = make_float4(out[i][4], out[i][5], out[i][6], out[i][7]);
            } else {
                if (j0 + 4 <= H)
                    *(float4*)yr = make_float4(out[i][0], out[i][1], out[i][2], out[i][3]);
                if (j0 + 8 <= H)
                    *(float4*)(yr + 4) = make_float4(out[i][4], out[i][5], out[i][6], out[i][7]);
            }
        }
        __syncthreads();   // hs ready for step t+1

#pragma unroll
        for (int i = 0; i < 4; i++)
#pragma unroll
            for (int c = 0; c < 8; c++) xp[i][c] = xn[i][c];
    }
}

// ---------------- launch ----------------
extern "C" void kernel_launch(void* const* d_in, const int* in_sizes, int n_in,
                              void* d_out, int out_size)
{
    (void)in_sizes; (void)n_in; (void)out_size;
    const float* x    = (const float*)d_in[0];
    const float* wih0 = (const float*)d_in[1];
    const float* whh0 = (const float*)d_in[2];
    const float* bi0  = (const float*)d_in[3];
    const float* bh0  = (const float*)d_in[4];
    const float* wih1 = (const float*)d_in[5];
    const float* whh1 = (const float*)d_in[6];
    const float* bi1  = (const float*)d_in[7];
    const float* bh1  = (const float*)d_in[8];
    const float* wih2 = (const float*)d_in[9];
    const float* whh2 = (const float*)d_in[10];
    const float* bi2  = (const float*)d_in[11];
    const float* bh2  = (const float*)d_in[12];
    float* out = (float*)d_out;

    void* p;
    cudaGetSymbolAddress(&p, g_bufA);   float* bufA = (float*)p;
    cudaGetSymbolAddress(&p, g_bufB);   float* bufB = (float*)p;
    cudaGetSymbolAddress(&p, g_wih0t);  float* W0i  = (float*)p;
    cudaGetSymbolAddress(&p, g_whh0t);  float* W0h  = (float*)p;
    cudaGetSymbolAddress(&p, g_b0);     float* Bs0  = (float*)p;
    cudaGetSymbolAddress(&p, g_wih1t);  float* W1i  = (float*)p;
    cudaGetSymbolAddress(&p, g_whh1t);  float* W1h  = (float*)p;
    cudaGetSymbolAddress(&p, g_b1);     float* Bs1  = (float*)p;
    cudaGetSymbolAddress(&p, g_wih2t);  float* W2i  = (float*)p;
    cudaGetSymbolAddress(&p, g_whh2t);  float* W2h  = (float*)p;
    cudaGetSymbolAddress(&p, g_b2);     float* Bs2  = (float*)p;

    // smem: ws (K*NP f32) + xs (128*CSP2 float2) + bs (NP f32)
    const int smem_p0 = 84  * 128 * 4 + 128 * 15 * 8 + 128 * 4;  // 58,880
    const int smem_p1 = 128 * 128 * 4 + 128 * 17 * 8 + 128 * 4;  // 83,456
    const int smem_p2 = 128 * 96  * 4 + 128 * 17 * 8 + 96  * 4;  // 66,944
    // smem: ws (H*HP f32) + hs (BB*HS2 float2)
    const int smem_r1 = 128 * 128 * 4 + 32 * 65 * 8;             // 82,176
    const int smem_r2 = 84  * 96  * 4 + 32 * 43 * 8;             // 43,264

    cudaFuncSetAttribute((const void*)proj_kernel<84, 128, 128, 28, 128>,
                         cudaFuncAttributeMaxDynamicSharedMemorySize, smem_p0);
    cudaFuncSetAttribute((const void*)proj_kernel<128, 128, 128, 32, 128>,
                         cudaFuncAttributeMaxDynamicSharedMemorySize, smem_p1);
    cudaFuncSetAttribute((const void*)proj_kernel<128, 84, 96, 32, 96>,
                         cudaFuncAttributeMaxDynamicSharedMemorySize, smem_p2);
    cudaFuncSetAttribute((const void*)rnn_kernel<128, 128, 32>,
                         cudaFuncAttributeMaxDynamicSharedMemorySize, smem_r1);
    cudaFuncSetAttribute((const void*)rnn_kernel<84, 96, 32>,
                         cudaFuncAttributeMaxDynamicSharedMemorySize, smem_r2);

    prep_kernel<<<96, 256>>>(wih0, whh0, bi0, bh0,
                             wih1, whh1, bi1, bh1,
                             wih2, whh2, bi2, bh2);

    const int mblocks = (int)(M / 128);   // 4096
    const int rblocks = B / 32;           // 256

    // Layer 0: x (K=84) -> bufA, scan in-place
    proj_kernel<84, 128, 128, 28, 128><<<mblocks, 128, smem_p0>>>(x, W0i, Bs0, bufA);
    rnn_kernel<128, 128, 32><<<rblocks, 128, smem_r1>>>(bufA, W0h, bufA);

    // Layer 1: bufA -> bufB, scan in-place
    proj_kernel<128, 128, 128, 32, 128><<<mblocks, 128, smem_p1>>>(bufA, W1i, Bs1, bufB);
    rnn_kernel<128, 128, 32><<<rblocks, 128, smem_r1>>>(bufB, W1h, bufB);

    // Layer 2: bufB -> bufA (stride 84), scan writes final output
    proj_kernel<128, 84, 96, 32, 96><<<mblocks, 96, smem_p2>>>(bufB, W2i, Bs2, bufA);
    rnn_kernel<84, 96, 32><<<rblocks, 96, smem_r2>>>(bufA, W2h, out);
}

// round 15
// speedup vs baseline: 1.8532x; 1.1393x over previous
#include <cuda_runtime.h>
#include <cuda_bf16.h>

// ---------------------------------------------------------------------------
// 3-layer Elman RNN: (B=8192, T=64) 84 -> 128 -> 128 -> 84
// v8: proj1/proj2 via legacy mma.sync m16n8k16 bf16 (family-safe HMMA),
//     hi/lo-split 3-pass, fp32 accum. rnn layers 0/1 emit packed
//     (bf16hi<<16)|bf16lo. proj0 + recurrences on the FFMA2 path (v5).
// ---------------------------------------------------------------------------

namespace {
constexpr int B  = 8192;
constexpr int T  = 64;
constexpr int IN = 84;
constexpr int H1 = 128;
constexpr int H2 = 84;
constexpr long M = (long)B * T;          // 524288 rows
constexpr int NTILES = (int)(M / 128);   // 4096
}

__device__ float g_bufA[(size_t)M * H1];
__device__ float g_bufB[(size_t)M * H1];

// FFMA2-path weights
__device__ float g_wih0t[IN * H1];
__device__ float g_whh0t[H1 * H1];
__device__ float g_b0[H1];
__device__ float g_whh1t[H1 * H1];
__device__ float g_b1[H1];
__device__ float g_whh2t[IN * 96];
__device__ float g_b2[96];
// Tensor-path B fragments (hi/lo bf16x2, mma-fragment order)
__device__ unsigned g_bf1hi[16 * 512];
__device__ unsigned g_bf1lo[16 * 512];
__device__ unsigned g_bf2hi[12 * 512];
__device__ unsigned g_bf2lo[12 * 512];

// ---------------- packed f32x2 helpers ----------------
__device__ __forceinline__ unsigned long long pk2(float lo, float hi) {
    unsigned long long r;
    asm("mov.b64 %0, {%1, %2};" : "=l"(r) : "f"(lo), "f"(hi));
    return r;
}
__device__ __forceinline__ void upk2(float& lo, float& hi, unsigned long long v) {
    asm("mov.b64 {%0, %1}, %2;" : "=f"(lo), "=f"(hi) : "l"(v));
}
__device__ __forceinline__ void fma2(unsigned long long& d, unsigned long long a,
                                     unsigned long long b) {
    asm("fma.rn.f32x2 %0, %1, %2, %0;" : "+l"(d) : "l"(a), "l"(b));
}
__device__ __forceinline__ float fast_tanh(float x) {
    float e, r;
    asm("ex2.approx.f32 %0, %1;" : "=f"(e) : "f"(x * 2.885390081777927f));
    asm("rcp.approx.f32 %0, %1;" : "=f"(r) : "f"(e + 1.0f));
    return fmaf(-2.0f, r, 1.0f);
}
__device__ __forceinline__ unsigned short bhi16(float v) {
    return __bfloat16_as_ushort(__float2bfloat16(v));
}
__device__ __forceinline__ unsigned short blo16(float v) {
    float h = __bfloat162float(__float2bfloat16(v));
    return __bfloat16_as_ushort(__float2bfloat16(v - h));
}
__device__ __forceinline__ unsigned packsplit(float v) {
    return ((unsigned)bhi16(v) << 16) | blo16(v);
}
// bf16 mma: D += A(16x16) * B(16x8)^T-ish (row.col)
__device__ __forceinline__ void mma16816(float4& d, unsigned a0, unsigned a1,
                                         unsigned a2, unsigned a3,
                                         unsigned b0, unsigned b1) {
    asm volatile(
        "mma.sync.aligned.m16n8k16.row.col.f32.bf16.bf16.f32 "
        "{%0,%1,%2,%3},{%4,%5,%6,%7},{%8,%9},{%0,%1,%2,%3};"
        : "+f"(d.x), "+f"(d.y), "+f"(d.z), "+f"(d.w)
        : "r"(a0), "r"(a1), "r"(a2), "r"(a3), "r"(b0), "r"(b1));
}

// ---------------- weight prep ----------------
__global__ void prep_kernel(
    const float* __restrict__ wih0, const float* __restrict__ whh0,
    const float* __restrict__ bi0,  const float* __restrict__ bh0,
    const float* __restrict__ wih1, const float* __restrict__ whh1,
    const float* __restrict__ bi1,  const float* __restrict__ bh1,
    const float* __restrict__ wih2, const float* __restrict__ whh2,
    const float* __restrict__ bi2,  const float* __restrict__ bh2)
{
    int tid = blockIdx.x * blockDim.x + threadIdx.x;
    int nt  = gridDim.x * blockDim.x;
    for (int i = tid; i < IN * H1; i += nt) {
        int k = i / H1, n = i % H1;
        g_wih0t[i] = wih0[n * IN + k];
    }
    for (int i = tid; i < H1 * H1; i += nt) {
        int k = i / H1, n = i % H1;
        g_whh0t[i] = whh0[n * H1 + k];
        g_whh1t[i] = whh1[n * H1 + k];
    }
    for (int i = tid; i < IN * 96; i += nt) {
        int k = i / 96, n = i % 96;
        g_whh2t[i] = (n < H2) ? whh2[n * H2 + k] : 0.f;
    }
    // B fragments: frag idx = ((nb*8 + s)*32 + t)*2 + reg
    //   n = nb*8 + t/4 ; k = 2*kp ; s = kp/8 ; reg = (kp%8<4)?0:1 ; t%4 = kp%4
    for (int i = tid; i < 128 * 64; i += nt) {
        int n = i / 64, kp = i % 64, k = 2 * kp;
        int s = kp / 8, reg = (kp % 8 < 4) ? 0 : 1;
        int t = (n % 8) * 4 + (kp % 4);
        int idx = (((n / 8) * 8 + s) * 32 + t) * 2 + reg;
        float v0 = wih1[n * 128 + k], v1 = wih1[n * 128 + k + 1];
        g_bf1hi[idx] = ((unsigned)bhi16(v1) << 16) | bhi16(v0);
        g_bf1lo[idx] = ((unsigned)blo16(v1) << 16) | blo16(v0);
    }
    for (int i = tid; i < 96 * 64; i += nt) {
        int n = i / 64, kp = i % 64, k = 2 * kp;
        int s = kp / 8, reg = (kp % 8 < 4) ? 0 : 1;
        int t = (n % 8) * 4 + (kp % 4);
        int idx = (((n / 8) * 8 + s) * 32 + t) * 2 + reg;
        float v0 = (n < H2) ? wih2[n * 128 + k]     : 0.f;
        float v1 = (n < H2) ? wih2[n * 128 + k + 1] : 0.f;
        g_bf2hi[idx] = ((unsigned)bhi16(v1) << 16) | bhi16(v0);
        g_bf2lo[idx] = ((unsigned)blo16(v1) << 16) | blo16(v0);
    }
    for (int i = tid; i < H1; i += nt) {
        g_b0[i] = bi0[i] + bh0[i];
        g_b1[i] = bi1[i] + bh1[i];
    }
    for (int i = tid; i < 96; i += nt)
        g_b2[i] = (i < H2) ? (bi2[i] + bh2[i]) : 0.f;
}

// ---------------- HMMA projection ----------------
// Y[m,0..NOUT) = split(Ap[m,0..128)) @ split(W[NB8*8,128))^T + bias
// Persistent 148 CTAs x 256 thr. Warp tile m32 x n64 (4m x 2n warps).
// A staged per 64-k chunk as hi/lo bf16x2 planes, row stride 36 u32.
template<int NB8, int NOUT>
__global__ void __launch_bounds__(256, 1)
tproj_kernel(const unsigned* __restrict__ Ap,
             const unsigned* __restrict__ Bh, const unsigned* __restrict__ Bl,
             const float* __restrict__ bias, float* __restrict__ Y)
{
    constexpr int AS  = 36;                 // A plane row stride (u32)
    constexpr int APL = 128 * AS;           // 4608 u32 per plane
    constexpr int NBW = NB8 / 2;            // nb per warp

    extern __shared__ unsigned smu[];
    unsigned* hiA  = smu;
    unsigned* loA  = smu + APL;
    unsigned* bh_s = smu + 2 * APL;
    unsigned* bl_s = bh_s + NB8 * 512;
    float*    bs   = (float*)(bl_s + NB8 * 512);

    const int tid = threadIdx.x;
    const int w   = tid >> 5, t = tid & 31;
    const int mrow0 = (w & 3) * 32;         // warp m base
    const int nb0   = (w >> 2) * NBW;       // warp nb base
    const int tq = t & 3, tr = t >> 2;

    for (int i = tid; i < NB8 * 512; i += 256) {
        bh_s[i] = Bh[i];
        bl_s[i] = Bl[i];
    }
    for (int i = tid; i < NB8 * 8; i += 256) bs[i] = (i < NOUT) ? bias[i] : 0.f;

    for (int tile = blockIdx.x; tile < NTILES; tile += gridDim.x) {
        const size_t m0 = (size_t)tile * 128;
        float4 acc[2][NBW];
#pragma unroll
        for (int mb = 0; mb < 2; mb++)
#pragma unroll
            for (int nb = 0; nb < NBW; nb++)
                acc[mb][nb] = make_float4(0.f, 0.f, 0.f, 0.f);

        for (int c = 0; c < 2; c++) {
            __syncthreads();   // prior chunk reads (and B/bias load) complete
            // stage A chunk: 2048 uint4, PRMT-split into hi/lo planes
#pragma unroll
            for (int it = 0; it < 8; it++) {
                int idx = it * 256 + tid;
                int row = idx >> 4, g = idx & 15;
                const uint4 p = *(const uint4*)(Ap + (m0 + row) * 128 + c * 64 + g * 4);
                *(uint2*)&hiA[row * AS + 2 * g] =
                    make_uint2(__byte_perm(p.x, p.y, 0x7632), __byte_perm(p.z, p.w, 0x7632));
                *(uint2*)&loA[row * AS + 2 * g] =
                    make_uint2(__byte_perm(p.x, p.y, 0x5410), __byte_perm(p.z, p.w, 0x5410));
            }
            __syncthreads();

#pragma unroll
            for (int s = 0; s < 4; s++) {
                unsigned ah[2][4], al[2][4];
#pragma unroll
                for (int mb = 0; mb < 2; mb++) {
                    const int m = mrow0 + 16 * mb + tr;
                    ah[mb][0] = hiA[m * AS + s * 8 + tq];
                    ah[mb][1] = hiA[(m + 8) * AS + s * 8 + tq];
                    ah[mb][2] = hiA[m * AS + s * 8 + 4 + tq];
                    ah[mb][3] = hiA[(m + 8) * AS + s * 8 + 4 + tq];
                    al[mb][0] = loA[m * AS + s * 8 + tq];
                    al[mb][1] = loA[(m + 8) * AS + s * 8 + tq];
                    al[mb][2] = loA[m * AS + s * 8 + 4 + tq];
                    al[mb][3] = loA[(m + 8) * AS + s * 8 + 4 + tq];
                }
                const int sg = c * 4 + s;
#pragma unroll
                for (int nb = 0; nb < NBW; nb++) {
                    const int bi = (((nb0 + nb) * 8 + sg) * 32 + t) * 2;
                    const uint2 bh = *(const uint2*)&bh_s[bi];
                    const uint2 bl = *(const uint2*)&bl_s[bi];
#pragma unroll
                    for (int mb = 0; mb < 2; mb++) {
                        mma16816(acc[mb][nb], ah[mb][0], ah[mb][1], ah[mb][2], ah[mb][3], bh.x, bh.y);
                        mma16816(acc[mb][nb], al[mb][0], al[mb][1], al[mb][2], al[mb][3], bh.x, bh.y);
                        mma16816(acc[mb][nb], ah[mb][0], ah[mb][1], ah[mb][2], ah[mb][3], bl.x, bl.y);
                    }
                }
            }
        }

        // epilogue: c0,c1 -> (row, col..col+1); c2,c3 -> (row+8, ...)
#pragma unroll
        for (int mb = 0; mb < 2; mb++) {
            const int r1 = mrow0 + 16 * mb + tr;
#pragma unroll
            for (int nb = 0; nb < NBW; nb++) {
                const int col = (nb0 + nb) * 8 + tq * 2;
                if (col < NOUT) {
                    const float b0 = bs[col], b1 = bs[col + 1];
                    float4 a = acc[mb][nb];
                    *(float2*)&Y[(m0 + r1) * NOUT + col] =
                        make_float2(a.x + b0, a.y + b1);
                    *(float2*)&Y[(m0 + r1 + 8) * NOUT + col] =
                        make_float2(a.z + b0, a.w + b1);
                }
            }
        }
    }
}

// ---------------- input projection GEMM (FFMA2, layer 0 only) ----------------
template<int K, int N, int NP, int CH, int NTHR>
__global__ void __launch_bounds__(NTHR, 2)
proj_kernel(const float* __restrict__ X, const float* __restrict__ Wt,
            const float* __restrict__ bias, float* __restrict__ Y)
{
    constexpr int NCH  = K / CH;
    constexpr int KP   = CH / 2;
    constexpr int CSP2 = (KP % 2 == 0) ? KP + 1 : KP;
    constexpr int VEC  = (CH % 8 == 0) ? 4 : 2;
    constexpr int TOT  = 128 * CH / VEC;
    constexpr int NLD  = (TOT + NTHR - 1) / NTHR;

    extern __shared__ float sm[];
    float*  ws = sm;
    float2* xs = (float2*)(ws + K * NP);
    float*  bs = (float*)(xs + 128 * CSP2);

    const int tid = threadIdx.x;
    const size_t m0 = (size_t)blockIdx.x * 128;
    const float* Xg = X + m0 * K;

    for (int i = tid; i < K * NP / 4; i += NTHR)
        ((float4*)ws)[i] = ((const float4*)Wt)[i];
    for (int i = tid; i < NP; i += NTHR) bs[i] = bias[i];

    const int ig = tid % 16;
    const int jg = tid / 16;
    const int j0 = jg * 16;

    float pf[NLD][VEC];
#pragma unroll
    for (int it = 0; it < NLD; it++) {
        int idx = tid + it * NTHR;
        if ((TOT % NTHR == 0) || idx < TOT) {
            int e = idx * VEC;
            int row = e / CH, kc = e % CH;
            const float* p = Xg + (size_t)row * K + kc;
            if (VEC == 4) {
                float4 v = *(const float4*)p;
                pf[it][0] = v.x; pf[it][1] = v.y; pf[it][2] = v.z; pf[it][3] = v.w;
            } else {
                float2 v = *(const float2*)p;
                pf[it][0] = v.x; pf[it][1] = v.y;
            }
        }
    }
    __syncthreads();

    unsigned long long acc[8][8];
#pragma unroll
    for (int q = 0; q < 8; q++) {
        unsigned long long bq = pk2(bs[j0 + 2 * q], bs[j0 + 2 * q + 1]);
#pragma unroll
        for (int i = 0; i < 8; i++) acc[i][q] = bq;
    }

    for (int c = 0; c < NCH; c++) {
#pragma unroll
        for (int it = 0; it < NLD; it++) {
            int idx = tid + it * NTHR;
            if ((TOT % NTHR == 0) || idx < TOT) {
                int e = idx * VEC;
                int row = e / CH, kc = e % CH;
                xs[row * CSP2 + kc / 2] = make_float2(pf[it][0], pf[it][1]);
                if (VEC == 4)
                    xs[row * CSP2 + kc / 2 + 1] = make_float2(pf[it][2], pf[it][3]);
            }
        }
        __syncthreads();
        if (c + 1 < NCH) {
#pragma unroll
            for (int it = 0; it < NLD; it++) {
                int idx = tid + it * NTHR;
                if ((TOT % NTHR == 0) || idx < TOT) {
                    int e = idx * VEC;
                    int row = e / CH, kc = e % CH;
                    const float* p = Xg + (size_t)row * K + (c + 1) * CH + kc;
                    if (VEC == 4) {
                        float4 v = *(const float4*)p;
                        pf[it][0] = v.x; pf[it][1] = v.y; pf[it][2] = v.z; pf[it][3] = v.w;
                    } else {
                        float2 v = *(const float2*)p;
                        pf[it][0] = v.x; pf[it][1] = v.y;
                    }
                }
            }
        }
#pragma unroll 2
        for (int kk = 0; kk < KP; kk++) {
            const int k = c * CH + 2 * kk;
            const ulonglong2 w0a = *(const ulonglong2*)&ws[k * NP + j0];
            const ulonglong2 w0b = *(const ulonglong2*)&ws[k * NP + j0 + 4];
            const ulonglong2 w0c = *(const ulonglong2*)&ws[k * NP + j0 + 8];
            const ulonglong2 w0d = *(const ulonglong2*)&ws[k * NP + j0 + 12];
            const ulonglong2 w1a = *(const ulonglong2*)&ws[(k + 1) * NP + j0];
            const ulonglong2 w1b = *(const ulonglong2*)&ws[(k + 1) * NP + j0 + 4];
            const ulonglong2 w1c = *(const ulonglong2*)&ws[(k + 1) * NP + j0 + 8];
            const ulonglong2 w1d = *(const ulonglong2*)&ws[(k + 1) * NP + j0 + 12];
#pragma unroll
            for (int i = 0; i < 8; i++) {
                const float2 xv = xs[(ig + i * 16) * CSP2 + kk];
                const unsigned long long a0 = pk2(xv.x, xv.x);
                const unsigned long long a1 = pk2(xv.y, xv.y);
                fma2(acc[i][0], a0, w0a.x); fma2(acc[i][1], a0, w0a.y);
                fma2(acc[i][2], a0, w0b.x); fma2(acc[i][3], a0, w0b.y);
                fma2(acc[i][4], a0, w0c.x); fma2(acc[i][5], a0, w0c.y);
                fma2(acc[i][6], a0, w0d.x); fma2(acc[i][7], a0, w0d.y);
                fma2(acc[i][0], a1, w1a.x); fma2(acc[i][1], a1, w1a.y);
                fma2(acc[i][2], a1, w1b.x); fma2(acc[i][3], a1, w1b.y);
                fma2(acc[i][4], a1, w1c.x); fma2(acc[i][5], a1, w1c.y);
                fma2(acc[i][6], a1, w1d.x); fma2(acc[i][7], a1, w1d.y);
            }
        }
        if (c + 1 < NCH) __syncthreads();
    }

#pragma unroll
    for (int i = 0; i < 8; i++) {
        const int r = ig + i * 16;
        float* yr = Y + (m0 + r) * N;
        float o[16];
#pragma unroll
        for (int q = 0; q < 8; q++) upk2(o[2 * q], o[2 * q + 1], acc[i][q]);
#pragma unroll
        for (int v = 0; v < 4; v++) {
            const int n = j0 + 4 * v;
            if (N == NP || n + 4 <= N)
                *(float4*)&yr[n] = make_float4(o[4*v], o[4*v+1], o[4*v+2], o[4*v+3]);
        }
    }
}

// ---------------- recurrence scan (FFMA2), optional packed output ----------
template<int H, int HP, int BB, bool PACK>
__global__ void __launch_bounds__((HP / 8) * (BB / 4), 2)
rnn_kernel(const float* __restrict__ XP, const float* __restrict__ Wt,
           float* __restrict__ Yout)
{
    constexpr int NTHR = (HP / 8) * (BB / 4);
    constexpr int RG   = BB / 4;
    constexpr int KPH  = H / 2;
    constexpr int HS2  = (KPH % 2 == 0) ? KPH + 1 : KPH;

    extern __shared__ float sm[];
    float*  ws = sm;
    float2* hs = (float2*)(ws + H * HP);

    const int tid = threadIdx.x;
    const size_t b0 = (size_t)blockIdx.x * BB;

    for (int i = tid; i < H * HP / 4; i += NTHR)
        ((float4*)ws)[i] = ((const float4*)Wt)[i];
    for (int i = tid; i < BB * HS2; i += NTHR) hs[i] = make_float2(0.f, 0.f);
    __syncthreads();

    const int ig = tid % RG;
    const int jg = tid / RG;
    const int j0 = jg * 8;

    float xp[4][8];
#pragma unroll
    for (int i = 0; i < 4; i++) {
        const int r = ig + i * RG;
        const float* p = XP + ((b0 + r) * T + 0) * H + j0;
        float4 a = (j0 + 4 <= H) ? *(const float4*)p       : make_float4(0,0,0,0);
        float4 b = (j0 + 8 <= H) ? *(const float4*)(p + 4) : make_float4(0,0,0,0);
        xp[i][0]=a.x; xp[i][1]=a.y; xp[i][2]=a.z; xp[i][3]=a.w;
        xp[i][4]=b.x; xp[i][5]=b.y; xp[i][6]=b.z; xp[i][7]=b.w;
    }

    for (int t = 0; t < T; t++) {
        float xn[4][8];
        if (t + 1 < T) {
#pragma unroll
            for (int i = 0; i < 4; i++) {
                const int r = ig + i * RG;
                const float* p = XP + ((b0 + r) * T + (t + 1)) * H + j0;
                float4 a = (j0 + 4 <= H) ? *(const float4*)p       : make_float4(0,0,0,0);
                float4 b = (j0 + 8 <= H) ? *(const float4*)(p + 4) : make_float4(0,0,0,0);
                xn[i][0]=a.x; xn[i][1]=a.y; xn[i][2]=a.z; xn[i][3]=a.w;
                xn[i][4]=b.x; xn[i][5]=b.y; xn[i][6]=b.z; xn[i][7]=b.w;
            }
        } else {
#pragma unroll
            for (int i = 0; i < 4; i++)
#pragma unroll
                for (int c = 0; c < 8; c++) xn[i][c] = 0.f;
        }

        unsigned long long acc[4][4];
#pragma unroll
        for (int i = 0; i < 4; i++)
#pragma unroll
            for (int q = 0; q < 4; q++)
                acc[i][q] = pk2(xp[i][2 * q], xp[i][2 * q + 1]);

#pragma unroll 4
        for (int kk = 0; kk < KPH; kk++) {
            const int k = 2 * kk;
            const ulonglong2 wA = *(const ulonglong2*)&ws[k * HP + j0];
            const ulonglong2 wB = *(const ulonglong2*)&ws[k * HP + j0 + 4];
            const ulonglong2 wC = *(const ulonglong2*)&ws[(k + 1) * HP + j0];
            const ulonglong2 wD = *(const ulonglong2*)&ws[(k + 1) * HP + j0 + 4];
#pragma unroll
            for (int i = 0; i < 4; i++) {
                const float2 hv = hs[(ig + i * RG) * HS2 + kk];
                const unsigned long long a0 = pk2(hv.x, hv.x);
                const unsigned long long a1 = pk2(hv.y, hv.y);
                fma2(acc[i][0], a0, wA.x); fma2(acc[i][1], a0, wA.y);
                fma2(acc[i][2], a0, wB.x); fma2(acc[i][3], a0, wB.y);
                fma2(acc[i][0], a1, wC.x); fma2(acc[i][1], a1, wC.y);
                fma2(acc[i][2], a1, wD.x); fma2(acc[i][3], a1, wD.y);
            }
        }

        float out[4][8];
#pragma unroll
        for (int i = 0; i < 4; i++)
#pragma unroll
            for (int q = 0; q < 4; q++) {
                float lo, hi;
                upk2(lo, hi, acc[i][q]);
                out[i][2 * q]     = fast_tanh(lo);
                out[i][2 * q + 1] = fast_tanh(hi);
            }

        __syncthreads();
#pragma unroll
        for (int i = 0; i < 4; i++) {
            const int r = ig + i * RG;
            float2* hr = hs + r * HS2 + j0 / 2;
#pragma unroll
            for (int q = 0; q < 4; q++) {
                if (H == HP || j0 + 2 * q + 1 < H)
                    hr[q] = make_float2(out[i][2 * q], out[i][2 * q + 1]);
            }
            float* yr = Yout + ((b0 + r) * T + t) * H + j0;
            if (PACK) {
                unsigned* yu = (unsigned*)yr;
                unsigned po[8];
#pragma unroll
                for (int c = 0; c < 8; c++) po[c] = packsplit(out[i][c]);
                *(uint4*)yu       = make_uint4(po[0], po[1], po[2], po[3]);
                *(uint4*)(yu + 4) = make_uint4(po[4], po[5], po[6], po[7]);
            } else if (H == HP) {
                *(float4*)yr       = make_float4(out[i][0], out[i][1], out[i][2], out[i][3]);
                *(float4*)(yr + 4) = make_float4(out[i][4], out[i][5], out[i][6], out[i][7]);
            } else {
                if (j0 + 4 <= H)
                    *(float4*)yr = make_float4(out[i][0], out[i][1], out[i][2], out[i][3]);
                if (j0 + 8 <= H)
                    *(float4*)(yr + 4) = make_float4(out[i][4], out[i][5], out[i][6], out[i][7]);
            }
        }
        __syncthreads();

#pragma unroll
        for (int i = 0; i < 4; i++)
#pragma unroll
            for (int c = 0; c < 8; c++) xp[i][c] = xn[i][c];
    }
}

// ---------------- launch ----------------
extern "C" void kernel_launch(void* const* d_in, const int* in_sizes, int n_in,
                              void* d_out, int out_size)
{
    (void)in_sizes; (void)n_in; (void)out_size;
    const float* x    = (const float*)d_in[0];
    const float* wih0 = (const float*)d_in[1];
    const float* whh0 = (const float*)d_in[2];
    const float* bi0  = (const float*)d_in[3];
    const float* bh0  = (const float*)d_in[4];
    const float* wih1 = (const float*)d_in[5];
    const float* whh1 = (const float*)d_in[6];
    const float* bi1  = (const float*)d_in[7];
    const float* bh1  = (const float*)d_in[8];
    const float* wih2 = (const float*)d_in[9];
    const float* whh2 = (const float*)d_in[10];
    const float* bi2  = (const float*)d_in[11];
    const float* bh2  = (const float*)d_in[12];
    float* out = (float*)d_out;

    void* p;
    cudaGetSymbolAddress(&p, g_bufA);   float*    bufA = (float*)p;
    cudaGetSymbolAddress(&p, g_bufB);   float*    bufB = (float*)p;
    cudaGetSymbolAddress(&p, g_wih0t);  float*    W0i  = (float*)p;
    cudaGetSymbolAddress(&p, g_whh0t);  float*    W0h  = (float*)p;
    cudaGetSymbolAddress(&p, g_b0);     float*    Bs0  = (float*)p;
    cudaGetSymbolAddress(&p, g_whh1t);  float*    W1h  = (float*)p;
    cudaGetSymbolAddress(&p, g_b1);     float*    Bs1  = (float*)p;
    cudaGetSymbolAddress(&p, g_whh2t);  float*    W2h  = (float*)p;
    cudaGetSymbolAddress(&p, g_b2);     float*    Bs2  = (float*)p;
    cudaGetSymbolAddress(&p, g_bf1hi);  unsigned* B1h  = (unsigned*)p;
    cudaGetSymbolAddress(&p, g_bf1lo);  unsigned* B1l  = (unsigned*)p;
    cudaGetSymbolAddress(&p, g_bf2hi);  unsigned* B2h  = (unsigned*)p;
    cudaGetSymbolAddress(&p, g_bf2lo);  unsigned* B2l  = (unsigned*)p;

    const int smem_p0 = 84  * 128 * 4 + 128 * 15 * 8 + 128 * 4;
    const int smem_r1 = 128 * 128 * 4 + 32 * 65 * 8;
    const int smem_r2 = 84  * 96  * 4 + 32 * 43 * 8;
    const int smem_t1 = (2 * 128 * 36 + 2 * 16 * 512 + 16 * 8) * 4;  // 102,912
    const int smem_t2 = (2 * 128 * 36 + 2 * 12 * 512 + 12 * 8) * 4;  //  86,400

    cudaFuncSetAttribute((const void*)proj_kernel<84, 128, 128, 28, 128>,
                         cudaFuncAttributeMaxDynamicSharedMemorySize, smem_p0);
    cudaFuncSetAttribute((const void*)tproj_kernel<16, 128>,
                         cudaFuncAttributeMaxDynamicSharedMemorySize, smem_t1);
    cudaFuncSetAttribute((const void*)tproj_kernel<12, 84>,
                         cudaFuncAttributeMaxDynamicSharedMemorySize, smem_t2);
    cudaFuncSetAttribute((const void*)rnn_kernel<128, 128, 32, true>,
                         cudaFuncAttributeMaxDynamicSharedMemorySize, smem_r1);
    cudaFuncSetAttribute((const void*)rnn_kernel<84, 96, 32, false>,
                         cudaFuncAttributeMaxDynamicSharedMemorySize, smem_r2);

    prep_kernel<<<96, 256>>>(wih0, whh0, bi0, bh0,
                             wih1, whh1, bi1, bh1,
                             wih2, whh2, bi2, bh2);

    const int mblocks = (int)(M / 128);   // 4096
    const int rblocks = B / 32;           // 256

    // Layer 0: FFMA2 proj, rnn writes PACKED h into bufA
    proj_kernel<84, 128, 128, 28, 128><<<mblocks, 128, smem_p0>>>(x, W0i, Bs0, bufA);
    rnn_kernel<128, 128, 32, true><<<rblocks, 128, smem_r1>>>(bufA, W0h, bufA);

    // Layer 1: HMMA proj (packed bufA -> fp32 bufB), rnn packs into bufB
    tproj_kernel<16, 128><<<148, 256, smem_t1>>>((const unsigned*)bufA, B1h, B1l, Bs1, bufB);
    rnn_kernel<128, 128, 32, true><<<rblocks, 128, smem_r1>>>(bufB, W1h, bufB);

    // Layer 2: HMMA proj (packed bufB -> fp32 bufA, N=84), rnn writes out
    tproj_kernel<12, 84><<<148, 256, smem_t2>>>((const unsigned*)bufB, B2h, B2l, Bs2, bufA);
    rnn_kernel<84, 96, 32, false><<<rblocks, 96, smem_r2>>>(bufA, W2h, out);
}

// round 16
// speedup vs baseline: 1.8563x; 1.0017x over previous
#include <cuda_runtime.h>
#include <cuda_bf16.h>

// ---------------------------------------------------------------------------
// 3-layer Elman RNN: (B=8192, T=64) 84 -> 128 -> 128 -> 84
// v8: proj1/proj2 via legacy mma.sync m16n8k16 bf16 (family-safe HMMA),
//     hi/lo-split 3-pass, fp32 accum. rnn layers 0/1 emit packed
//     (bf16hi<<16)|bf16lo. proj0 + recurrences on the FFMA2 path (v5).
// ---------------------------------------------------------------------------

namespace {
constexpr int B  = 8192;
constexpr int T  = 64;
constexpr int IN = 84;
constexpr int H1 = 128;
constexpr int H2 = 84;
constexpr long M = (long)B * T;          // 524288 rows
constexpr int NTILES = (int)(M / 128);   // 4096
}

__device__ float g_bufA[(size_t)M * H1];
__device__ float g_bufB[(size_t)M * H1];

// FFMA2-path weights
__device__ float g_wih0t[IN * H1];
__device__ float g_whh0t[H1 * H1];
__device__ float g_b0[H1];
__device__ float g_whh1t[H1 * H1];
__device__ float g_b1[H1];
__device__ float g_whh2t[IN * 96];
__device__ float g_b2[96];
// Tensor-path B fragments (hi/lo bf16x2, mma-fragment order)
__device__ unsigned g_bf1hi[16 * 512];
__device__ unsigned g_bf1lo[16 * 512];
__device__ unsigned g_bf2hi[12 * 512];
__device__ unsigned g_bf2lo[12 * 512];

// ---------------- packed f32x2 helpers ----------------
__device__ __forceinline__ unsigned long long pk2(float lo, float hi) {
    unsigned long long r;
    asm("mov.b64 %0, {%1, %2};" : "=l"(r) : "f"(lo), "f"(hi));
    return r;
}
__device__ __forceinline__ void upk2(float& lo, float& hi, unsigned long long v) {
    asm("mov.b64 {%0, %1}, %2;" : "=f"(lo), "=f"(hi) : "l"(v));
}
__device__ __forceinline__ void fma2(unsigned long long& d, unsigned long long a,
                                     unsigned long long b) {
    asm("fma.rn.f32x2 %0, %1, %2, %0;" : "+l"(d) : "l"(a), "l"(b));
}
__device__ __forceinline__ float fast_tanh(float x) {
    float e, r;
    asm("ex2.approx.f32 %0, %1;" : "=f"(e) : "f"(x * 2.885390081777927f));
    asm("rcp.approx.f32 %0, %1;" : "=f"(r) : "f"(e + 1.0f));
    return fmaf(-2.0f, r, 1.0f);
}
__device__ __forceinline__ unsigned short bhi16(float v) {
    return __bfloat16_as_ushort(__float2bfloat16(v));
}
__device__ __forceinline__ unsigned short blo16(float v) {
    float h = __bfloat162float(__float2bfloat16(v));
    return __bfloat16_as_ushort(__float2bfloat16(v - h));
}
__device__ __forceinline__ unsigned packsplit(float v) {
    return ((unsigned)bhi16(v) << 16) | blo16(v);
}
// bf16 mma: D += A(16x16) * B(16x8)^T-ish (row.col)
__device__ __forceinline__ void mma16816(float4& d, unsigned a0, unsigned a1,
                                         unsigned a2, unsigned a3,
                                         unsigned b0, unsigned b1) {
    asm volatile(
        "mma.sync.aligned.m16n8k16.row.col.f32.bf16.bf16.f32 "
        "{%0,%1,%2,%3},{%4,%5,%6,%7},{%8,%9},{%0,%1,%2,%3};"
        : "+f"(d.x), "+f"(d.y), "+f"(d.z), "+f"(d.w)
        : "r"(a0), "r"(a1), "r"(a2), "r"(a3), "r"(b0), "r"(b1));
}

// ---------------- weight prep ----------------
__global__ void prep_kernel(
    const float* __restrict__ wih0, const float* __restrict__ whh0,
    const float* __restrict__ bi0,  const float* __restrict__ bh0,
    const float* __restrict__ wih1, const float* __restrict__ whh1,
    const float* __restrict__ bi1,  const float* __restrict__ bh1,
    const float* __restrict__ wih2, const float* __restrict__ whh2,
    const float* __restrict__ bi2,  const float* __restrict__ bh2)
{
    int tid = blockIdx.x * blockDim.x + threadIdx.x;
    int nt  = gridDim.x * blockDim.x;
    for (int i = tid; i < IN * H1; i += nt) {
        int k = i / H1, n = i % H1;
        g_wih0t[i] = wih0[n * IN + k];
    }
    for (int i = tid; i < H1 * H1; i += nt) {
        int k = i / H1, n = i % H1;
        g_whh0t[i] = whh0[n * H1 + k];
        g_whh1t[i] = whh1[n * H1 + k];
    }
    for (int i = tid; i < IN * 96; i += nt) {
        int k = i / 96, n = i % 96;
        g_whh2t[i] = (n < H2) ? whh2[n * H2 + k] : 0.f;
    }
    // B fragments: frag idx = ((nb*8 + s)*32 + t)*2 + reg
    //   n = nb*8 + t/4 ; k = 2*kp ; s = kp/8 ; reg = (kp%8<4)?0:1 ; t%4 = kp%4
    for (int i = tid; i < 128 * 64; i += nt) {
        int n = i / 64, kp = i % 64, k = 2 * kp;
        int s = kp / 8, reg = (kp % 8 < 4) ? 0 : 1;
        int t = (n % 8) * 4 + (kp % 4);
        int idx = (((n / 8) * 8 + s) * 32 + t) * 2 + reg;
        float v0 = wih1[n * 128 + k], v1 = wih1[n * 128 + k + 1];
        g_bf1hi[idx] = ((unsigned)bhi16(v1) << 16) | bhi16(v0);
        g_bf1lo[idx] = ((unsigned)blo16(v1) << 16) | blo16(v0);
    }
    for (int i = tid; i < 96 * 64; i += nt) {
        int n = i / 64, kp = i % 64, k = 2 * kp;
        int s = kp / 8, reg = (kp % 8 < 4) ? 0 : 1;
        int t = (n % 8) * 4 + (kp % 4);
        int idx = (((n / 8) * 8 + s) * 32 + t) * 2 + reg;
        float v0 = (n < H2) ? wih2[n * 128 + k]     : 0.f;
        float v1 = (n < H2) ? wih2[n * 128 + k + 1] : 0.f;
        g_bf2hi[idx] = ((unsigned)bhi16(v1) << 16) | bhi16(v0);
        g_bf2lo[idx] = ((unsigned)blo16(v1) << 16) | blo16(v0);
    }
    for (int i = tid; i < H1; i += nt) {
        g_b0[i] = bi0[i] + bh0[i];
        g_b1[i] = bi1[i] + bh1[i];
    }
    for (int i = tid; i < 96; i += nt)
        g_b2[i] = (i < H2) ? (bi2[i] + bh2[i]) : 0.f;
}

// ---------------- HMMA projection ----------------
// Y[m,0..NOUT) = split(Ap[m,0..128)) @ split(W[NB8*8,128))^T + bias
// Persistent 148 CTAs x 256 thr. Warp tile m32 x n64 (4m x 2n warps).
// A staged per 64-k chunk as hi/lo bf16x2 planes, row stride 36 u32.
template<int NB8, int NOUT>
__global__ void __launch_bounds__(256, 1)
tproj_kernel(const unsigned* __restrict__ Ap,
             const unsigned* __restrict__ Bh, const unsigned* __restrict__ Bl,
             const float* __restrict__ bias, float* __restrict__ Y)
{
    constexpr int AS  = 36;                 // A plane row stride (u32)
    constexpr int APL = 128 * AS;           // 4608 u32 per plane
    constexpr int NBW = NB8 / 2;            // nb per warp

    extern __shared__ unsigned smu[];
    unsigned* hiA  = smu;
    unsigned* loA  = smu + APL;
    unsigned* bh_s = smu + 2 * APL;
    unsigned* bl_s = bh_s + NB8 * 512;
    float*    bs   = (float*)(bl_s + NB8 * 512);

    const int tid = threadIdx.x;
    const int w   = tid >> 5, t = tid & 31;
    const int mrow0 = (w & 3) * 32;         // warp m base
    const int nb0   = (w >> 2) * NBW;       // warp nb base
    const int tq = t & 3, tr = t >> 2;

    for (int i = tid; i < NB8 * 512; i += 256) {
        bh_s[i] = Bh[i];
        bl_s[i] = Bl[i];
    }
    for (int i = tid; i < NB8 * 8; i += 256) bs[i] = (i < NOUT) ? bias[i] : 0.f;

    for (int tile = blockIdx.x; tile < NTILES; tile += gridDim.x) {
        const size_t m0 = (size_t)tile * 128;
        float4 acc[2][NBW];
#pragma unroll
        for (int mb = 0; mb < 2; mb++)
#pragma unroll
            for (int nb = 0; nb < NBW; nb++)
                acc[mb][nb] = make_float4(0.f, 0.f, 0.f, 0.f);

        for (int c = 0; c < 2; c++) {
            __syncthreads();   // prior chunk reads (and B/bias load) complete
            // stage A chunk: 2048 uint4, PRMT-split into hi/lo planes
#pragma unroll
            for (int it = 0; it < 8; it++) {
                int idx = it * 256 + tid;
                int row = idx >> 4, g = idx & 15;
                const uint4 p = *(const uint4*)(Ap + (m0 + row) * 128 + c * 64 + g * 4);
                *(uint2*)&hiA[row * AS + 2 * g] =
                    make_uint2(__byte_perm(p.x, p.y, 0x7632), __byte_perm(p.z, p.w, 0x7632));
                *(uint2*)&loA[row * AS + 2 * g] =
                    make_uint2(__byte_perm(p.x, p.y, 0x5410), __byte_perm(p.z, p.w, 0x5410));
            }
            __syncthreads();

#pragma unroll
            for (int s = 0; s < 4; s++) {
                unsigned ah[2][4], al[2][4];
#pragma unroll
                for (int mb = 0; mb < 2; mb++) {
                    const int m = mrow0 + 16 * mb + tr;
                    ah[mb][0] = hiA[m * AS + s * 8 + tq];
                    ah[mb][1] = hiA[(m + 8) * AS + s * 8 + tq];
                    ah[mb][2] = hiA[m * AS + s * 8 + 4 + tq];
                    ah[mb][3] = hiA[(m + 8) * AS + s * 8 + 4 + tq];
                    al[mb][0] = loA[m * AS + s * 8 + tq];
                    al[mb][1] = loA[(m + 8) * AS + s * 8 + tq];
                    al[mb][2] = loA[m * AS + s * 8 + 4 + tq];
                    al[mb][3] = loA[(m + 8) * AS + s * 8 + 4 + tq];
                }
                const int sg = c * 4 + s;
#pragma unroll
                for (int nb = 0; nb < NBW; nb++) {
                    const int bi = (((nb0 + nb) * 8 + sg) * 32 + t) * 2;
                    const uint2 bh = *(const uint2*)&bh_s[bi];
                    const uint2 bl = *(const uint2*)&bl_s[bi];
#pragma unroll
                    for (int mb = 0; mb < 2; mb++) {
                        mma16816(acc[mb][nb], ah[mb][0], ah[mb][1], ah[mb][2], ah[mb][3], bh.x, bh.y);
                        mma16816(acc[mb][nb], al[mb][0], al[mb][1], al[mb][2], al[mb][3], bh.x, bh.y);
                        mma16816(acc[mb][nb], ah[mb][0], ah[mb][1], ah[mb][2], ah[mb][3], bl.x, bl.y);
                    }
                }
            }
        }

        // epilogue: c0,c1 -> (row, col..col+1); c2,c3 -> (row+8, ...)
#pragma unroll
        for (int mb = 0; mb < 2; mb++) {
            const int r1 = mrow0 + 16 * mb + tr;
#pragma unroll
            for (int nb = 0; nb < NBW; nb++) {
                const int col = (nb0 + nb) * 8 + tq * 2;
                if (col < NOUT) {
                    const float b0 = bs[col], b1 = bs[col + 1];
                    float4 a = acc[mb][nb];
                    *(float2*)&Y[(m0 + r1) * NOUT + col] =
                        make_float2(a.x + b0, a.y + b1);
                    *(float2*)&Y[(m0 + r1 + 8) * NOUT + col] =
                        make_float2(a.z + b0, a.w + b1);
                }
            }
        }
    }
}

// ---------------- input projection GEMM (FFMA2, layer 0 only) ----------------
template<int K, int N, int NP, int CH, int NTHR>
__global__ void __launch_bounds__(NTHR, 2)
proj_kernel(const float* __restrict__ X, const float* __restrict__ Wt,
            const float* __restrict__ bias, float* __restrict__ Y)
{
    constexpr int NCH  = K / CH;
    constexpr int KP   = CH / 2;
    constexpr int CSP2 = (KP % 2 == 0) ? KP + 1 : KP;
    constexpr int VEC  = (CH % 8 == 0) ? 4 : 2;
    constexpr int TOT  = 128 * CH / VEC;
    constexpr int NLD  = (TOT + NTHR - 1) / NTHR;

    extern __shared__ float sm[];
    float*  ws = sm;
    float2* xs = (float2*)(ws + K * NP);
    float*  bs = (float*)(xs + 128 * CSP2);

    const int tid = threadIdx.x;
    const size_t m0 = (size_t)blockIdx.x * 128;
    const float* Xg = X + m0 * K;

    for (int i = tid; i < K * NP / 4; i += NTHR)
        ((float4*)ws)[i] = ((const float4*)Wt)[i];
    for (int i = tid; i < NP; i += NTHR) bs[i] = bias[i];

    const int ig = tid % 16;
    const int jg = tid / 16;
    const int j0 = jg * 16;

    float pf[NLD][VEC];
#pragma unroll
    for (int it = 0; it < NLD; it++) {
        int idx = tid + it * NTHR;
        if ((TOT % NTHR == 0) || idx < TOT) {
            int e = idx * VEC;
            int row = e / CH, kc = e % CH;
            const float* p = Xg + (size_t)row * K + kc;
            if (VEC == 4) {
                float4 v = *(const float4*)p;
                pf[it][0] = v.x; pf[it][1] = v.y; pf[it][2] = v.z; pf[it][3] = v.w;
            } else {
                float2 v = *(const float2*)p;
                pf[it][0] = v.x; pf[it][1] = v.y;
            }
        }
    }
    __syncthreads();

    unsigned long long acc[8][8];
#pragma unroll
    for (int q = 0; q < 8; q++) {
        unsigned long long bq = pk2(bs[j0 + 2 * q], bs[j0 + 2 * q + 1]);
#pragma unroll
        for (int i = 0; i < 8; i++) acc[i][q] = bq;
    }

    for (int c = 0; c < NCH; c++) {
#pragma unroll
        for (int it = 0; it < NLD; it++) {
            int idx = tid + it * NTHR;
            if ((TOT % NTHR == 0) || idx < TOT) {
                int e = idx * VEC;
                int row = e / CH, kc = e % CH;
                xs[row * CSP2 + kc / 2] = make_float2(pf[it][0], pf[it][1]);
                if (VEC == 4)
                    xs[row * CSP2 + kc / 2 + 1] = make_float2(pf[it][2], pf[it][3]);
            }
        }
        __syncthreads();
        if (c + 1 < NCH) {
#pragma unroll
            for (int it = 0; it < NLD; it++) {
                int idx = tid + it * NTHR;
                if ((TOT % NTHR == 0) || idx < TOT) {
                    int e = idx * VEC;
                    int row = e / CH, kc = e % CH;
                    const float* p = Xg + (size_t)row * K + (c + 1) * CH + kc;
                    if (VEC == 4) {
                        float4 v = *(const float4*)p;
                        pf[it][0] = v.x; pf[it][1] = v.y; pf[it][2] = v.z; pf[it][3] = v.w;
                    } else {
                        float2 v = *(const float2*)p;
                        pf[it][0] = v.x; pf[it][1] = v.y;
                    }
                }
            }
        }
#pragma unroll 2
        for (int kk = 0; kk < KP; kk++) {
            const int k = c * CH + 2 * kk;
            const ulonglong2 w0a = *(const ulonglong2*)&ws[k * NP + j0];
            const ulonglong2 w0b = *(const ulonglong2*)&ws[k * NP + j0 + 4];
            const ulonglong2 w0c = *(const ulonglong2*)&ws[k * NP + j0 + 8];
            const ulonglong2 w0d = *(const ulonglong2*)&ws[k * NP + j0 + 12];
            const ulonglong2 w1a = *(const ulonglong2*)&ws[(k + 1) * NP + j0];
            const ulonglong2 w1b = *(const ulonglong2*)&ws[(k + 1) * NP + j0 + 4];
            const ulonglong2 w1c = *(const ulonglong2*)&ws[(k + 1) * NP + j0 + 8];
            const ulonglong2 w1d = *(const ulonglong2*)&ws[(k + 1) * NP + j0 + 12];
#pragma unroll
            for (int i = 0; i < 8; i++) {
                const float2 xv = xs[(ig + i * 16) * CSP2 + kk];
                const unsigned long long a0 = pk2(xv.x, xv.x);
                const unsigned long long a1 = pk2(xv.y, xv.y);
                fma2(acc[i][0], a0, w0a.x); fma2(acc[i][1], a0, w0a.y);
                fma2(acc[i][2], a0, w0b.x); fma2(acc[i][3], a0, w0b.y);
                fma2(acc[i][4], a0, w0c.x); fma2(acc[i][5], a0, w0c.y);
                fma2(acc[i][6], a0, w0d.x); fma2(acc[i][7], a0, w0d.y);
                fma2(acc[i][0], a1, w1a.x); fma2(acc[i][1], a1, w1a.y);
                fma2(acc[i][2], a1, w1b.x); fma2(acc[i][3], a1, w1b.y);
                fma2(acc[i][4], a1, w1c.x); fma2(acc[i][5], a1, w1c.y);
                fma2(acc[i][6], a1, w1d.x); fma2(acc[i][7], a1, w1d.y);
            }
        }
        if (c + 1 < NCH) __syncthreads();
    }

#pragma unroll
    for (int i = 0; i < 8; i++) {
        const int r = ig + i * 16;
        float* yr = Y + (m0 + r) * N;
        float o[16];
#pragma unroll
        for (int q = 0; q < 8; q++) upk2(o[2 * q], o[2 * q + 1], acc[i][q]);
#pragma unroll
        for (int v = 0; v < 4; v++) {
            const int n = j0 + 4 * v;
            if (N == NP || n + 4 <= N)
                *(float4*)&yr[n] = make_float4(o[4*v], o[4*v+1], o[4*v+2], o[4*v+3]);
        }
    }
}

// ---------------- recurrence scan (FFMA2), optional packed output ----------
template<int H, int HP, int BB, bool PACK>
__global__ void __launch_bounds__((HP / 8) * (BB / 4), 2)
rnn_kernel(const float* __restrict__ XP, const float* __restrict__ Wt,
           float* __restrict__ Yout)
{
    constexpr int NTHR = (HP / 8) * (BB / 4);
    constexpr int RG   = BB / 4;
    constexpr int KPH  = H / 2;
    constexpr int HS2  = (KPH % 2 == 0) ? KPH + 1 : KPH;

    extern __shared__ float sm[];
    float*  ws = sm;
    float2* hs = (float2*)(ws + H * HP);

    const int tid = threadIdx.x;
    const size_t b0 = (size_t)blockIdx.x * BB;

    for (int i = tid; i < H * HP / 4; i += NTHR)
        ((float4*)ws)[i] = ((const float4*)Wt)[i];
    for (int i = tid; i < BB * HS2; i += NTHR) hs[i] = make_float2(0.f, 0.f);
    __syncthreads();

    const int ig = tid % RG;
    const int jg = tid / RG;
    const int j0 = jg * 8;

    float xp[4][8];
#pragma unroll
    for (int i = 0; i < 4; i++) {
        const int r = ig + i * RG;
        const float* p = XP + ((b0 + r) * T + 0) * H + j0;
        float4 a = (j0 + 4 <= H) ? *(const float4*)p       : make_float4(0,0,0,0);
        float4 b = (j0 + 8 <= H) ? *(const float4*)(p + 4) : make_float4(0,0,0,0);
        xp[i][0]=a.x; xp[i][1]=a.y; xp[i][2]=a.z; xp[i][3]=a.w;
        xp[i][4]=b.x; xp[i][5]=b.y; xp[i][6]=b.z; xp[i][7]=b.w;
    }

    for (int t = 0; t < T; t++) {
        float xn[4][8];
        if (t + 1 < T) {
#pragma unroll
            for (int i = 0; i < 4; i++) {
                const int r = ig + i * RG;
                const float* p = XP + ((b0 + r) * T + (t + 1)) * H + j0;
                float4 a = (j0 + 4 <= H) ? *(const float4*)p       : make_float4(0,0,0,0);
                float4 b = (j0 + 8 <= H) ? *(const float4*)(p + 4) : make_float4(0,0,0,0);
                xn[i][0]=a.x; xn[i][1]=a.y; xn[i][2]=a.z; xn[i][3]=a.w;
                xn[i][4]=b.x; xn[i][5]=b.y; xn[i][6]=b.z; xn[i][7]=b.w;
            }
        } else {
#pragma unroll
            for (int i = 0; i < 4; i++)
#pragma unroll
                for (int c = 0; c < 8; c++) xn[i][c] = 0.f;
        }

        unsigned long long acc[4][4];
#pragma unroll
        for (int i = 0; i < 4; i++)
#pragma unroll
            for (int q = 0; q < 4; q++)
                acc[i][q] = pk2(xp[i][2 * q], xp[i][2 * q + 1]);

#pragma unroll 4
        for (int kk = 0; kk < KPH; kk++) {
            const int k = 2 * kk;
            const ulonglong2 wA = *(const ulonglong2*)&ws[k * HP + j0];
            const ulonglong2 wB = *(const ulonglong2*)&ws[k * HP + j0 + 4];
            const ulonglong2 wC = *(const ulonglong2*)&ws[(k + 1) * HP + j0];
            const ulonglong2 wD = *(const ulonglong2*)&ws[(k + 1) * HP + j0 + 4];
#pragma unroll
            for (int i = 0; i < 4; i++) {
                const float2 hv = hs[(ig + i * RG) * HS2 + kk];
                const unsigned long long a0 = pk2(hv.x, hv.x);
                const unsigned long long a1 = pk2(hv.y, hv.y);
                fma2(acc[i][0], a0, wA.x); fma2(acc[i][1], a0, wA.y);
                fma2(acc[i][2], a0, wB.x); fma2(acc[i][3], a0, wB.y);
                fma2(acc[i][0], a1, wC.x); fma2(acc[i][1], a1, wC.y);
                fma2(acc[i][2], a1, wD.x); fma2(acc[i][3], a1, wD.y);
            }
        }

        float out[4][8];
#pragma unroll
        for (int i = 0; i < 4; i++)
#pragma unroll
            for (int q = 0; q < 4; q++) {
                float lo, hi;
                upk2(lo, hi, acc[i][q]);
                out[i][2 * q]     = fast_tanh(lo);
                out[i][2 * q + 1] = fast_tanh(hi);
            }

        __syncthreads();
#pragma unroll
        for (int i = 0; i < 4; i++) {
            const int r = ig + i * RG;
            float2* hr = hs + r * HS2 + j0 / 2;
#pragma unroll
            for (int q = 0; q < 4; q++) {
                if (H == HP || j0 + 2 * q + 1 < H)
                    hr[q] = make_float2(out[i][2 * q], out[i][2 * q + 1]);
            }
            float* yr = Yout + ((b0 + r) * T + t) * H + j0;
            if (PACK) {
                unsigned* yu = (unsigned*)yr;
                unsigned po[8];
#pragma unroll
                for (int c = 0; c < 8; c++) po[c] = packsplit(out[i][c]);
                *(uint4*)yu       = make_uint4(po[0], po[1], po[2], po[3]);
                *(uint4*)(yu + 4) = make_uint4(po[4], po[5], po[6], po[7]);
            } else if (H == HP) {
                *(float4*)yr       = make_float4(out[i][0], out[i][1], out[i][2], out[i][3]);
                *(float4*)(yr + 4) = make_float4(out[i][4], out[i][5], out[i][6], out[i][7]);
            } else {
                if (j0 + 4 <= H)
                    *(float4*)yr = make_float4(out[i][0], out[i][1], out[i][2], out[i][3]);
                if (j0 + 8 <= H)
                    *(float4*)(yr + 4) = make_float4(out[i][4], out[i][5], out[i][6], out[i][7]);
            }
        }
        __syncthreads();

#pragma unroll
        for (int i = 0; i < 4; i++)
#pragma unroll
            for (int c = 0; c < 8; c++) xp[i][c] = xn[i][c];
    }
}

// ---------------- launch ----------------
extern "C" void kernel_launch(void* const* d_in, const int* in_sizes, int n_in,
                              void* d_out, int out_size)
{
    (void)in_sizes; (void)n_in; (void)out_size;
    const float* x    = (const float*)d_in[0];
    const float* wih0 = (const float*)d_in[1];
    const float* whh0 = (const float*)d_in[2];
    const float* bi0  = (const float*)d_in[3];
    const float* bh0  = (const float*)d_in[4];
    const float* wih1 = (const float*)d_in[5];
    const float* whh1 = (const float*)d_in[6];
    const float* bi1  = (const float*)d_in[7];
    const float* bh1  = (const float*)d_in[8];
    const float* wih2 = (const float*)d_in[9];
    const float* whh2 = (const float*)d_in[10];
    const float* bi2  = (const float*)d_in[11];
    const float* bh2  = (const float*)d_in[12];
    float* out = (float*)d_out;

    void* p;
    cudaGetSymbolAddress(&p, g_bufA);   float*    bufA = (float*)p;
    cudaGetSymbolAddress(&p, g_bufB);   float*    bufB = (float*)p;
    cudaGetSymbolAddress(&p, g_wih0t);  float*    W0i  = (float*)p;
    cudaGetSymbolAddress(&p, g_whh0t);  float*    W0h  = (float*)p;
    cudaGetSymbolAddress(&p, g_b0);     float*    Bs0  = (float*)p;
    cudaGetSymbolAddress(&p, g_whh1t);  float*    W1h  = (float*)p;
    cudaGetSymbolAddress(&p, g_b1);     float*    Bs1  = (float*)p;
    cudaGetSymbolAddress(&p, g_whh2t);  float*    W2h  = (float*)p;
    cudaGetSymbolAddress(&p, g_b2);     float*    Bs2  = (float*)p;
    cudaGetSymbolAddress(&p, g_bf1hi);  unsigned* B1h  = (unsigned*)p;
    cudaGetSymbolAddress(&p, g_bf1lo);  unsigned* B1l  = (unsigned*)p;
    cudaGetSymbolAddress(&p, g_bf2hi);  unsigned* B2h  = (unsigned*)p;
    cudaGetSymbolAddress(&p, g_bf2lo);  unsigned* B2l  = (unsigned*)p;

    const int smem_p0 = 84  * 128 * 4 + 128 * 15 * 8 + 128 * 4;
    const int smem_r1 = 128 * 128 * 4 + 32 * 65 * 8;
    const int smem_r2 = 84  * 96  * 4 + 32 * 43 * 8;
    const int smem_t1 = (2 * 128 * 36 + 2 * 16 * 512 + 16 * 8) * 4;  // 102,912
    const int smem_t2 = (2 * 128 * 36 + 2 * 12 * 512 + 12 * 8) * 4;  //  86,400

    cudaFuncSetAttribute((const void*)proj_kernel<84, 128, 128, 28, 128>,
                         cudaFuncAttributeMaxDynamicSharedMemorySize, smem_p0);
    cudaFuncSetAttribute((const void*)tproj_kernel<16, 128>,
                         cudaFuncAttributeMaxDynamicSharedMemorySize, smem_t1);
    cudaFuncSetAttribute((const void*)tproj_kernel<12, 84>,
                         cudaFuncAttributeMaxDynamicSharedMemorySize, smem_t2);
    cudaFuncSetAttribute((const void*)rnn_kernel<128, 128, 32, true>,
                         cudaFuncAttributeMaxDynamicSharedMemorySize, smem_r1);
    cudaFuncSetAttribute((const void*)rnn_kernel<84, 96, 32, false>,
                         cudaFuncAttributeMaxDynamicSharedMemorySize, smem_r2);

    prep_kernel<<<96, 256>>>(wih0, whh0, bi0, bh0,
                             wih1, whh1, bi1, bh1,
                             wih2, whh2, bi2, bh2);

    const int mblocks = (int)(M / 128);   // 4096
    const int rblocks = B / 32;           // 256

    // Layer 0: FFMA2 proj, rnn writes PACKED h into bufA
    proj_kernel<84, 128, 128, 28, 128><<<mblocks, 128, smem_p0>>>(x, W0i, Bs0, bufA);
    rnn_kernel<128, 128, 32, true><<<rblocks, 128, smem_r1>>>(bufA, W0h, bufA);

    // Layer 1: HMMA proj (packed bufA -> fp32 bufB), rnn packs into bufB
    tproj_kernel<16, 128><<<148, 256, smem_t1>>>((const unsigned*)bufA, B1h, B1l, Bs1, bufB);
    rnn_kernel<128, 128, 32, true><<<rblocks, 128, smem_r1>>>(bufB, W1h, bufB);

    // Layer 2: HMMA proj (packed bufB -> fp32 bufA, N=84), rnn writes out
    tproj_kernel<12, 84><<<148, 256, smem_t2>>>((const unsigned*)bufB, B2h, B2l, Bs2, bufA);
    rnn_kernel<84, 96, 32, false><<<rblocks, 96, smem_r2>>>(bufA, W2h, out);
}

// round 17
// speedup vs baseline: 3.0158x; 1.6246x over previous
#include <cuda_runtime.h>
#include <cuda_bf16.h>

// ---------------------------------------------------------------------------
// 3-layer Elman RNN: (B=8192, T=64) 84 -> 128 -> 128 -> 84
// v9: ALL big GEMM work on HMMA (mma.sync m16n8k16 bf16, hi/lo 3-pass):
//     - proj1/proj2: persistent tproj (v8, validated)
//     - recurrences: NEW rnnh kernel — h kept in smem bf16x2 hi/lo planes,
//       W_hh fragments resident in smem, 2 syncs/step, packed output.
//     proj0 stays FFMA2.
// ---------------------------------------------------------------------------

namespace {
constexpr int B  = 8192;
constexpr int T  = 64;
constexpr int IN = 84;
constexpr int H1 = 128;
constexpr int H2 = 84;
constexpr long M = (long)B * T;          // 524288 rows
constexpr int NTILES = (int)(M / 128);   // 4096
}

__device__ float g_bufA[(size_t)M * H1];
__device__ float g_bufB[(size_t)M * H1];

// FFMA2-path weights (layer-0 projection)
__device__ float g_wih0t[IN * H1];
__device__ float g_b0[H1];
__device__ float g_b1[H1];
__device__ float g_b2[96];
// tproj B fragments (hi/lo bf16x2, validated mma-fragment order)
__device__ unsigned g_bf1hi[16 * 512];
__device__ unsigned g_bf1lo[16 * 512];
__device__ unsigned g_bf2hi[12 * 512];
__device__ unsigned g_bf2lo[12 * 512];
// recurrence W_hh fragments
__device__ unsigned g_rf0hi[16 * 8 * 64], g_rf0lo[16 * 8 * 64];
__device__ unsigned g_rf1hi[16 * 8 * 64], g_rf1lo[16 * 8 * 64];
__device__ unsigned g_rf2hi[12 * 6 * 64], g_rf2lo[12 * 6 * 64];

// ---------------- helpers ----------------
__device__ __forceinline__ unsigned long long pk2(float lo, float hi) {
    unsigned long long r;
    asm("mov.b64 %0, {%1, %2};" : "=l"(r) : "f"(lo), "f"(hi));
    return r;
}
__device__ __forceinline__ void upk2(float& lo, float& hi, unsigned long long v) {
    asm("mov.b64 {%0, %1}, %2;" : "=f"(lo), "=f"(hi) : "l"(v));
}
__device__ __forceinline__ void fma2(unsigned long long& d, unsigned long long a,
                                     unsigned long long b) {
    asm("fma.rn.f32x2 %0, %1, %2, %0;" : "+l"(d) : "l"(a), "l"(b));
}
__device__ __forceinline__ float fast_tanh(float x) {
    float e, r;
    asm("ex2.approx.f32 %0, %1;" : "=f"(e) : "f"(x * 2.885390081777927f));
    asm("rcp.approx.f32 %0, %1;" : "=f"(r) : "f"(e + 1.0f));
    return fmaf(-2.0f, r, 1.0f);
}
__device__ __forceinline__ unsigned short bhi16(float v) {
    return __bfloat16_as_ushort(__float2bfloat16(v));
}
__device__ __forceinline__ unsigned short blo16(float v) {
    float h = __bfloat162float(__float2bfloat16(v));
    return __bfloat16_as_ushort(__float2bfloat16(v - h));
}
// packed pair: [31:16]=bf16(hi_elem), [15:0]=bf16(lo_elem)
__device__ __forceinline__ unsigned cvtbf2(float lo, float hi) {
    unsigned r;
    asm("cvt.rn.bf16x2.f32 %0, %1, %2;" : "=r"(r) : "f"(hi), "f"(lo));
    return r;
}
__device__ __forceinline__ void mma16816(float4& d, unsigned a0, unsigned a1,
                                         unsigned a2, unsigned a3,
                                         unsigned b0, unsigned b1) {
    asm volatile(
        "mma.sync.aligned.m16n8k16.row.col.f32.bf16.bf16.f32 "
        "{%0,%1,%2,%3},{%4,%5,%6,%7},{%8,%9},{%0,%1,%2,%3};"
        : "+f"(d.x), "+f"(d.y), "+f"(d.z), "+f"(d.w)
        : "r"(a0), "r"(a1), "r"(a2), "r"(a3), "r"(b0), "r"(b1));
}

// ---------------- weight prep ----------------
// frag idx (validated in v8): for W[n][k], kp=k/2:
//   idx = (((n/8)*KS + kp/8)*32 + (n%8)*4 + kp%4)*2 + ((kp%8)<4 ? 0 : 1)
__global__ void prep_kernel(
    const float* __restrict__ wih0, const float* __restrict__ whh0,
    const float* __restrict__ bi0,  const float* __restrict__ bh0,
    const float* __restrict__ wih1, const float* __restrict__ whh1,
    const float* __restrict__ bi1,  const float* __restrict__ bh1,
    const float* __restrict__ wih2, const float* __restrict__ whh2,
    const float* __restrict__ bi2,  const float* __restrict__ bh2)
{
    int tid = blockIdx.x * blockDim.x + threadIdx.x;
    int nt  = gridDim.x * blockDim.x;
    for (int i = tid; i < IN * H1; i += nt) {
        int k = i / H1, n = i % H1;
        g_wih0t[i] = wih0[n * IN + k];
    }
    // 128x128 frag packs: wih1 (tproj), whh0, whh1 (rnnh), KS=8
    for (int i = tid; i < 128 * 64; i += nt) {
        int n = i / 64, kp = i % 64, k = 2 * kp;
        int s = kp / 8, reg = (kp % 8 < 4) ? 0 : 1;
        int t = (n % 8) * 4 + (kp % 4);
        int idx = (((n / 8) * 8 + s) * 32 + t) * 2 + reg;
        float v0 = wih1[n * 128 + k], v1 = wih1[n * 128 + k + 1];
        g_bf1hi[idx] = ((unsigned)bhi16(v1) << 16) | bhi16(v0);
        g_bf1lo[idx] = ((unsigned)blo16(v1) << 16) | blo16(v0);
        v0 = whh0[n * 128 + k]; v1 = whh0[n * 128 + k + 1];
        g_rf0hi[idx] = ((unsigned)bhi16(v1) << 16) | bhi16(v0);
        g_rf0lo[idx] = ((unsigned)blo16(v1) << 16) | blo16(v0);
        v0 = whh1[n * 128 + k]; v1 = whh1[n * 128 + k + 1];
        g_rf1hi[idx] = ((unsigned)bhi16(v1) << 16) | bhi16(v0);
        g_rf1lo[idx] = ((unsigned)blo16(v1) << 16) | blo16(v0);
    }
    // wih2: 96n x 128k (rows >=84 zero), KS=8
    for (int i = tid; i < 96 * 64; i += nt) {
        int n = i / 64, kp = i % 64, k = 2 * kp;
        int s = kp / 8, reg = (kp % 8 < 4) ? 0 : 1;
        int t = (n % 8) * 4 + (kp % 4);
        int idx = (((n / 8) * 8 + s) * 32 + t) * 2 + reg;
        float v0 = (n < H2) ? wih2[n * 128 + k]     : 0.f;
        float v1 = (n < H2) ? wih2[n * 128 + k + 1] : 0.f;
        g_bf2hi[idx] = ((unsigned)bhi16(v1) << 16) | bhi16(v0);
        g_bf2lo[idx] = ((unsigned)blo16(v1) << 16) | blo16(v0);
    }
    // whh2: 96n x 96k (pad from 84x84), KS=6
    for (int i = tid; i < 96 * 48; i += nt) {
        int n = i / 48, kp = i % 48, k = 2 * kp;
        int s = kp / 8, reg = (kp % 8 < 4) ? 0 : 1;
        int t = (n % 8) * 4 + (kp % 4);
        int idx = (((n / 8) * 6 + s) * 32 + t) * 2 + reg;
        float v0 = (n < H2 && k < H2)     ? whh2[n * H2 + k]     : 0.f;
        float v1 = (n < H2 && k + 1 < H2) ? whh2[n * H2 + k + 1] : 0.f;
        g_rf2hi[idx] = ((unsigned)bhi16(v1) << 16) | bhi16(v0);
        g_rf2lo[idx] = ((unsigned)blo16(v1) << 16) | blo16(v0);
    }
    for (int i = tid; i < H1; i += nt) {
        g_b0[i] = bi0[i] + bh0[i];
        g_b1[i] = bi1[i] + bh1[i];
    }
    for (int i = tid; i < 96; i += nt)
        g_b2[i] = (i < H2) ? (bi2[i] + bh2[i]) : 0.f;
}

// ---------------- HMMA projection (unchanged from v8) ----------------
template<int NB8, int NOUT>
__global__ void __launch_bounds__(256, 1)
tproj_kernel(const unsigned* __restrict__ Ap,
             const unsigned* __restrict__ Bh, const unsigned* __restrict__ Bl,
             const float* __restrict__ bias, float* __restrict__ Y)
{
    constexpr int AS  = 36;
    constexpr int APL = 128 * AS;
    constexpr int NBW = NB8 / 2;

    extern __shared__ unsigned smu[];
    unsigned* hiA  = smu;
    unsigned* loA  = smu + APL;
    unsigned* bh_s = smu + 2 * APL;
    unsigned* bl_s = bh_s + NB8 * 512;
    float*    bs   = (float*)(bl_s + NB8 * 512);

    const int tid = threadIdx.x;
    const int w   = tid >> 5, t = tid & 31;
    const int mrow0 = (w & 3) * 32;
    const int nb0   = (w >> 2) * NBW;
    const int tq = t & 3, tr = t >> 2;

    for (int i = tid; i < NB8 * 512; i += 256) {
        bh_s[i] = Bh[i];
        bl_s[i] = Bl[i];
    }
    for (int i = tid; i < NB8 * 8; i += 256) bs[i] = (i < NOUT) ? bias[i] : 0.f;

    for (int tile = blockIdx.x; tile < NTILES; tile += gridDim.x) {
        const size_t m0 = (size_t)tile * 128;
        float4 acc[2][NBW];
#pragma unroll
        for (int mb = 0; mb < 2; mb++)
#pragma unroll
            for (int nb = 0; nb < NBW; nb++)
                acc[mb][nb] = make_float4(0.f, 0.f, 0.f, 0.f);

        for (int c = 0; c < 2; c++) {
            __syncthreads();
#pragma unroll
            for (int it = 0; it < 8; it++) {
                int idx = it * 256 + tid;
                int row = idx >> 4, g = idx & 15;
                const uint4 p = *(const uint4*)(Ap + (m0 + row) * 128 + c * 64 + g * 4);
                *(uint2*)&hiA[row * AS + 2 * g] =
                    make_uint2(__byte_perm(p.x, p.y, 0x7632), __byte_perm(p.z, p.w, 0x7632));
                *(uint2*)&loA[row * AS + 2 * g] =
                    make_uint2(__byte_perm(p.x, p.y, 0x5410), __byte_perm(p.z, p.w, 0x5410));
            }
            __syncthreads();

#pragma unroll
            for (int s = 0; s < 4; s++) {
                unsigned ah[2][4], al[2][4];
#pragma unroll
                for (int mb = 0; mb < 2; mb++) {
                    const int m = mrow0 + 16 * mb + tr;
                    ah[mb][0] = hiA[m * AS + s * 8 + tq];
                    ah[mb][1] = hiA[(m + 8) * AS + s * 8 + tq];
                    ah[mb][2] = hiA[m * AS + s * 8 + 4 + tq];
                    ah[mb][3] = hiA[(m + 8) * AS + s * 8 + 4 + tq];
                    al[mb][0] = loA[m * AS + s * 8 + tq];
                    al[mb][1] = loA[(m + 8) * AS + s * 8 + tq];
                    al[mb][2] = loA[m * AS + s * 8 + 4 + tq];
                    al[mb][3] = loA[(m + 8) * AS + s * 8 + 4 + tq];
                }
                const int sg = c * 4 + s;
#pragma unroll
                for (int nb = 0; nb < NBW; nb++) {
                    const int bi = (((nb0 + nb) * 8 + sg) * 32 + t) * 2;
                    const uint2 bh = *(const uint2*)&bh_s[bi];
                    const uint2 bl = *(const uint2*)&bl_s[bi];
#pragma unroll
                    for (int mb = 0; mb < 2; mb++) {
                        mma16816(acc[mb][nb], ah[mb][0], ah[mb][1], ah[mb][2], ah[mb][3], bh.x, bh.y);
                        mma16816(acc[mb][nb], al[mb][0], al[mb][1], al[mb][2], al[mb][3], bh.x, bh.y);
                        mma16816(acc[mb][nb], ah[mb][0], ah[mb][1], ah[mb][2], ah[mb][3], bl.x, bl.y);
                    }
                }
            }
        }

#pragma unroll
        for (int mb = 0; mb < 2; mb++) {
            const int r1 = mrow0 + 16 * mb + tr;
#pragma unroll
            for (int nb = 0; nb < NBW; nb++) {
                const int col = (nb0 + nb) * 8 + tq * 2;
                if (col < NOUT) {
                    const float b0 = bs[col], b1 = bs[col + 1];
                    float4 a = acc[mb][nb];
                    *(float2*)&Y[(m0 + r1) * NOUT + col] =
                        make_float2(a.x + b0, a.y + b1);
                    *(float2*)&Y[(m0 + r1 + 8) * NOUT + col] =
                        make_float2(a.z + b0, a.w + b1);
                }
            }
        }
    }
}

// ---------------- HMMA recurrence ----------------
// BB=64 rows/CTA, 256 thr (8 warps = 2 mgrp x 4 ngrp, warp tile m32 x n(NBW*8)).
// h kept in smem hi/lo bf16x2 planes (row stride NPAIR+4 u32, bank-clean).
// Per step: acc init = xp_t (prefetched), 3-pass split mma over KS k-steps,
// tanh, repack planes + packed/fp32 global store. 2 syncthreads per step.
template<int NB8, int KS, bool PACKOUT, int NOUT>
__global__ void __launch_bounds__(256, 1)
rnnh_kernel(const float* XP, const unsigned* __restrict__ Bh,
            const unsigned* __restrict__ Bl, void* Yout)
{
    constexpr int NBW   = NB8 / 4;
    constexpr int NPAIR = NB8 * 4;          // = padded H / 2
    constexpr int PST   = NPAIR + 4;        // plane row stride (u32)
    constexpr int FRAG  = NB8 * KS * 64;    // u32 per B plane
    constexpr int XS    = NOUT;             // XP row stride (fp32 elems)

    extern __shared__ unsigned smr[];
    unsigned* bh_s = smr;
    unsigned* bl_s = smr + FRAG;
    unsigned* Phi  = smr + 2 * FRAG;
    unsigned* Plo  = Phi + 64 * PST;

    const int tid = threadIdx.x;
    const int w = tid >> 5, t32 = tid & 31;
    const int tq = t32 & 3, tr = t32 >> 2;
    const int mg = (w & 1) * 32;
    const int nbase = (w >> 1) * NBW;
    const size_t b0 = (size_t)blockIdx.x * 64;

    for (int i = tid; i < FRAG / 4; i += 256) {
        ((uint4*)bh_s)[i] = ((const uint4*)Bh)[i];
        ((uint4*)bl_s)[i] = ((const uint4*)Bl)[i];
    }
    for (int i = tid; i < 64 * PST; i += 256) { Phi[i] = 0u; Plo[i] = 0u; }

    // xp prefetch (t = 0)
    float4 xn[2][NBW];
#pragma unroll
    for (int mb = 0; mb < 2; mb++)
#pragma unroll
        for (int nb = 0; nb < NBW; nb++) {
            const int r = mg + 16 * mb + tr;
            const int col = 2 * ((nbase + nb) * 4 + tq);
            if (col + 1 < NOUT || NOUT == NPAIR * 2) {
                const float* p = XP + ((b0 + r) * T + 0) * XS + col;
                float2 a = *(const float2*)p;
                float2 c2 = *(const float2*)(p + (size_t)8 * T * XS);
                xn[mb][nb] = make_float4(a.x, a.y, c2.x, c2.y);
            } else xn[mb][nb] = make_float4(0, 0, 0, 0);
        }
    __syncthreads();

    for (int t = 0; t < T; t++) {
        float4 acc[2][NBW];
#pragma unroll
        for (int mb = 0; mb < 2; mb++)
#pragma unroll
            for (int nb = 0; nb < NBW; nb++) acc[mb][nb] = xn[mb][nb];

        // prefetch xp for t+1 (overlaps k-loop; same-thread addresses only)
        if (t + 1 < T) {
#pragma unroll
            for (int mb = 0; mb < 2; mb++)
#pragma unroll
                for (int nb = 0; nb < NBW; nb++) {
                    const int r = mg + 16 * mb + tr;
                    const int col = 2 * ((nbase + nb) * 4 + tq);
                    if (col + 1 < NOUT || NOUT == NPAIR * 2) {
                        const float* p = XP + ((b0 + r) * T + (t + 1)) * XS + col;
                        float2 a = *(const float2*)p;
                        float2 c2 = *(const float2*)(p + (size_t)8 * T * XS);
                        xn[mb][nb] = make_float4(a.x, a.y, c2.x, c2.y);
                    } else xn[mb][nb] = make_float4(0, 0, 0, 0);
                }
        }

        // k-loop: 3-pass split mma
#pragma unroll
        for (int ks = 0; ks < KS; ks++) {
            unsigned ah[2][4], al[2][4];
#pragma unroll
            for (int mb = 0; mb < 2; mb++) {
                const int m = mg + 16 * mb + tr;
                const int g = ks * 8 + tq;
                ah[mb][0] = Phi[m * PST + g];
                ah[mb][1] = Phi[(m + 8) * PST + g];
                ah[mb][2] = Phi[m * PST + g + 4];
                ah[mb][3] = Phi[(m + 8) * PST + g + 4];
                al[mb][0] = Plo[m * PST + g];
                al[mb][1] = Plo[(m + 8) * PST + g];
                al[mb][2] = Plo[m * PST + g + 4];
                al[mb][3] = Plo[(m + 8) * PST + g + 4];
            }
#pragma unroll
            for (int nb = 0; nb < NBW; nb++) {
                const int bi = (((nbase + nb) * KS + ks) * 32 + t32) * 2;
                const uint2 bh = *(const uint2*)&bh_s[bi];
                const uint2 bl = *(const uint2*)&bl_s[bi];
#pragma unroll
                for (int mb = 0; mb < 2; mb++) {
                    mma16816(acc[mb][nb], ah[mb][0], ah[mb][1], ah[mb][2], ah[mb][3], bh.x, bh.y);
                    mma16816(acc[mb][nb], al[mb][0], al[mb][1], al[mb][2], al[mb][3], bh.x, bh.y);
                    mma16816(acc[mb][nb], ah[mb][0], ah[mb][1], ah[mb][2], ah[mb][3], bl.x, bl.y);
                }
            }
        }

        __syncthreads();   // all plane reads of h_{t-1} complete

        // epilogue: tanh, split, store planes + global
#pragma unroll
        for (int mb = 0; mb < 2; mb++) {
            const int r = mg + 16 * mb + tr;
#pragma unroll
            for (int nb = 0; nb < NBW; nb++) {
                const int c = (nbase + nb) * 4 + tq;
                float4 a = acc[mb][nb];
                const float v0 = fast_tanh(a.x), v1 = fast_tanh(a.y);
                const float v2 = fast_tanh(a.z), v3 = fast_tanh(a.w);
                // row r pair
                const unsigned ph0 = cvtbf2(v0, v1);
                const float h0 = __uint_as_float(ph0 << 16);
                const float h1 = __uint_as_float(ph0 & 0xffff0000u);
                const unsigned pl0 = cvtbf2(v0 - h0, v1 - h1);
                // row r+8 pair
                const unsigned ph1 = cvtbf2(v2, v3);
                const float h2 = __uint_as_float(ph1 << 16);
                const float h3 = __uint_as_float(ph1 & 0xffff0000u);
                const unsigned pl1 = cvtbf2(v2 - h2, v3 - h3);
                Phi[r * PST + c] = ph0;       Plo[r * PST + c] = pl0;
                Phi[(r + 8) * PST + c] = ph1; Plo[(r + 8) * PST + c] = pl1;

                const int col = 2 * c;
                if (PACKOUT) {
                    unsigned* Yu = (unsigned*)Yout;
                    *(uint2*)&Yu[((b0 + r) * T + t) * NOUT + col] =
                        make_uint2(__byte_perm(pl0, ph0, 0x5410),
                                   __byte_perm(pl0, ph0, 0x7632));
                    *(uint2*)&Yu[((b0 + r + 8) * T + t) * NOUT + col] =
                        make_uint2(__byte_perm(pl1, ph1, 0x5410),
                                   __byte_perm(pl1, ph1, 0x7632));
                } else if (col + 1 < NOUT) {
                    float* Yf = (float*)Yout;
                    *(float2*)&Yf[((b0 + r) * T + t) * NOUT + col] = make_float2(v0, v1);
                    *(float2*)&Yf[((b0 + r + 8) * T + t) * NOUT + col] = make_float2(v2, v3);
                }
            }
        }
        __syncthreads();   // planes hold h_t for next step
    }
}

// ---------------- input projection GEMM (FFMA2, layer 0) ----------------
template<int K, int N, int NP, int CH, int NTHR>
__global__ void __launch_bounds__(NTHR, 2)
proj_kernel(const float* __restrict__ X, const float* __restrict__ Wt,
            const float* __restrict__ bias, float* __restrict__ Y)
{
    constexpr int NCH  = K / CH;
    constexpr int KP   = CH / 2;
    constexpr int CSP2 = (KP % 2 == 0) ? KP + 1 : KP;
    constexpr int VEC  = (CH % 8 == 0) ? 4 : 2;
    constexpr int TOT  = 128 * CH / VEC;
    constexpr int NLD  = (TOT + NTHR - 1) / NTHR;

    extern __shared__ float sm[];
    float*  ws = sm;
    float2* xs = (float2*)(ws + K * NP);
    float*  bs = (float*)(xs + 128 * CSP2);

    const int tid = threadIdx.x;
    const size_t m0 = (size_t)blockIdx.x * 128;
    const float* Xg = X + m0 * K;

    for (int i = tid; i < K * NP / 4; i += NTHR)
        ((float4*)ws)[i] = ((const float4*)Wt)[i];
    for (int i = tid; i < NP; i += NTHR) bs[i] = bias[i];

    const int ig = tid % 16;
    const int jg = tid / 16;
    const int j0 = jg * 16;

    float pf[NLD][VEC];
#pragma unroll
    for (int it = 0; it < NLD; it++) {
        int idx = tid + it * NTHR;
        if ((TOT % NTHR == 0) || idx < TOT) {
            int e = idx * VEC;
            int row = e / CH, kc = e % CH;
            const float* p = Xg + (size_t)row * K + kc;
            if (VEC == 4) {
                float4 v = *(const float4*)p;
                pf[it][0] = v.x; pf[it][1] = v.y; pf[it][2] = v.z; pf[it][3] = v.w;
            } else {
                float2 v = *(const float2*)p;
                pf[it][0] = v.x; pf[it][1] = v.y;
            }
        }
    }
    __syncthreads();

    unsigned long long acc[8][8];
#pragma unroll
    for (int q = 0; q < 8; q++) {
        unsigned long long bq = pk2(bs[j0 + 2 * q], bs[j0 + 2 * q + 1]);
#pragma unroll
        for (int i = 0; i < 8; i++) acc[i][q] = bq;
    }

    for (int c = 0; c < NCH; c++) {
#pragma unroll
        for (int it = 0; it < NLD; it++) {
            int idx = tid + it * NTHR;
            if ((TOT % NTHR == 0) || idx < TOT) {
                int e = idx * VEC;
                int row = e / CH, kc = e % CH;
                xs[row * CSP2 + kc / 2] = make_float2(pf[it][0], pf[it][1]);
                if (VEC == 4)
                    xs[row * CSP2 + kc / 2 + 1] = make_float2(pf[it][2], pf[it][3]);
            }
        }
        __syncthreads();
        if (c + 1 < NCH) {
#pragma unroll
            for (int it = 0; it < NLD; it++) {
                int idx = tid + it * NTHR;
                if ((TOT % NTHR == 0) || idx < TOT) {
                    int e = idx * VEC;
                    int row = e / CH, kc = e % CH;
                    const float* p = Xg + (size_t)row * K + (c + 1) * CH + kc;
                    if (VEC == 4) {
                        float4 v = *(const float4*)p;
                        pf[it][0] = v.x; pf[it][1] = v.y; pf[it][2] = v.z; pf[it][3] = v.w;
                    } else {
                        float2 v = *(const float2*)p;
                        pf[it][0] = v.x; pf[it][1] = v.y;
                    }
                }
            }
        }
#pragma unroll 2
        for (int kk = 0; kk < KP; kk++) {
            const int k = c * CH + 2 * kk;
            const ulonglong2 w0a = *(const ulonglong2*)&ws[k * NP + j0];
            const ulonglong2 w0b = *(const ulonglong2*)&ws[k * NP + j0 + 4];
            const ulonglong2 w0c = *(const ulonglong2*)&ws[k * NP + j0 + 8];
            const ulonglong2 w0d = *(const ulonglong2*)&ws[k * NP + j0 + 12];
            const ulonglong2 w1a = *(const ulonglong2*)&ws[(k + 1) * NP + j0];
            const ulonglong2 w1b = *(const ulonglong2*)&ws[(k + 1) * NP + j0 + 4];
            const ulonglong2 w1c = *(const ulonglong2*)&ws[(k + 1) * NP + j0 + 8];
            const ulonglong2 w1d = *(const ulonglong2*)&ws[(k + 1) * NP + j0 + 12];
#pragma unroll
            for (int i = 0; i < 8; i++) {
                const float2 xv = xs[(ig + i * 16) * CSP2 + kk];
                const unsigned long long a0 = pk2(xv.x, xv.x);
                const unsigned long long a1 = pk2(xv.y, xv.y);
                fma2(acc[i][0], a0, w0a.x); fma2(acc[i][1], a0, w0a.y);
                fma2(acc[i][2], a0, w0b.x); fma2(acc[i][3], a0, w0b.y);
                fma2(acc[i][4], a0, w0c.x); fma2(acc[i][5], a0, w0c.y);
                fma2(acc[i][6], a0, w0d.x); fma2(acc[i][7], a0, w0d.y);
                fma2(acc[i][0], a1, w1a.x); fma2(acc[i][1], a1, w1a.y);
                fma2(acc[i][2], a1, w1b.x); fma2(acc[i][3], a1, w1b.y);
                fma2(acc[i][4], a1, w1c.x); fma2(acc[i][5], a1, w1c.y);
                fma2(acc[i][6], a1, w1d.x); fma2(acc[i][7], a1, w1d.y);
            }
        }
        if (c + 1 < NCH) __syncthreads();
    }

#pragma unroll
    for (int i = 0; i < 8; i++) {
        const int r = ig + i * 16;
        float* yr = Y + (m0 + r) * N;
        float o[16];
#pragma unroll
        for (int q = 0; q < 8; q++) upk2(o[2 * q], o[2 * q + 1], acc[i][q]);
#pragma unroll
        for (int v = 0; v < 4; v++) {
            const int n = j0 + 4 * v;
            if (N == NP || n + 4 <= N)
                *(float4*)&yr[n] = make_float4(o[4*v], o[4*v+1], o[4*v+2], o[4*v+3]);
        }
    }
}

// ---------------- launch ----------------
extern "C" void kernel_launch(void* const* d_in, const int* in_sizes, int n_in,
                              void* d_out, int out_size)
{
    (void)in_sizes; (void)n_in; (void)out_size;
    const float* x    = (const float*)d_in[0];
    const float* wih0 = (const float*)d_in[1];
    const float* whh0 = (const float*)d_in[2];
    const float* bi0  = (const float*)d_in[3];
    const float* bh0  = (const float*)d_in[4];
    const float* wih1 = (const float*)d_in[5];
    const float* whh1 = (const float*)d_in[6];
    const float* bi1  = (const float*)d_in[7];
    const float* bh1  = (const float*)d_in[8];
    const float* wih2 = (const float*)d_in[9];
    const float* whh2 = (const float*)d_in[10];
    const float* bi2  = (const float*)d_in[11];
    const float* bh2  = (const float*)d_in[12];
    float* out = (float*)d_out;

    void* p;
    cudaGetSymbolAddress(&p, g_bufA);   float*    bufA = (float*)p;
    cudaGetSymbolAddress(&p, g_bufB);   float*    bufB = (float*)p;
    cudaGetSymbolAddress(&p, g_wih0t);  float*    W0i  = (float*)p;
    cudaGetSymbolAddress(&p, g_b0);     float*    Bs0  = (float*)p;
    cudaGetSymbolAddress(&p, g_b1);     float*    Bs1  = (float*)p;
    cudaGetSymbolAddress(&p, g_b2);     float*    Bs2  = (float*)p;
    cudaGetSymbolAddress(&p, g_bf1hi);  unsigned* B1h  = (unsigned*)p;
    cudaGetSymbolAddress(&p, g_bf1lo);  unsigned* B1l  = (unsigned*)p;
    cudaGetSymbolAddress(&p, g_bf2hi);  unsigned* B2h  = (unsigned*)p;
    cudaGetSymbolAddress(&p, g_bf2lo);  unsigned* B2l  = (unsigned*)p;
    cudaGetSymbolAddress(&p, g_rf0hi);  unsigned* R0h  = (unsigned*)p;
    cudaGetSymbolAddress(&p, g_rf0lo);  unsigned* R0l  = (unsigned*)p;
    cudaGetSymbolAddress(&p, g_rf1hi);  unsigned* R1h  = (unsigned*)p;
    cudaGetSymbolAddress(&p, g_rf1lo);  unsigned* R1l  = (unsigned*)p;
    cudaGetSymbolAddress(&p, g_rf2hi);  unsigned* R2h  = (unsigned*)p;
    cudaGetSymbolAddress(&p, g_rf2lo);  unsigned* R2l  = (unsigned*)p;

    const int smem_p0  = 84 * 128 * 4 + 128 * 15 * 8 + 128 * 4;       // 58,880
    const int smem_t1  = (2 * 128 * 36 + 2 * 16 * 512 + 16 * 8) * 4;  // 102,912
    const int smem_t2  = (2 * 128 * 36 + 2 * 12 * 512 + 12 * 8) * 4;  //  86,400
    const int smem_rh1 = (2 * 8192 + 2 * 64 * 68) * 4;                // 100,352
    const int smem_rh2 = (2 * 4608 + 2 * 64 * 52) * 4;                //  63,488

    cudaFuncSetAttribute((const void*)proj_kernel<84, 128, 128, 28, 128>,
                         cudaFuncAttributeMaxDynamicSharedMemorySize, smem_p0);
    cudaFuncSetAttribute((const void*)tproj_kernel<16, 128>,
                         cudaFuncAttributeMaxDynamicSharedMemorySize, smem_t1);
    cudaFuncSetAttribute((const void*)tproj_kernel<12, 84>,
                         cudaFuncAttributeMaxDynamicSharedMemorySize, smem_t2);
    cudaFuncSetAttribute((const void*)rnnh_kernel<16, 8, true, 128>,
                         cudaFuncAttributeMaxDynamicSharedMemorySize, smem_rh1);
    cudaFuncSetAttribute((const void*)rnnh_kernel<12, 6, false, 84>,
                         cudaFuncAttributeMaxDynamicSharedMemorySize, smem_rh2);

    prep_kernel<<<96, 256>>>(wih0, whh0, bi0, bh0,
                             wih1, whh1, bi1, bh1,
                             wih2, whh2, bi2, bh2);

    const int mblocks = (int)(M / 128);   // 4096
    const int rblocks = B / 64;           // 128

    // Layer 0: FFMA2 proj -> fp32 bufA; HMMA rnn -> packed bufA (in place)
    proj_kernel<84, 128, 128, 28, 128><<<mblocks, 128, smem_p0>>>(x, W0i, Bs0, bufA);
    rnnh_kernel<16, 8, true, 128><<<rblocks, 256, smem_rh1>>>(bufA, R0h, R0l, bufA);

    // Layer 1: HMMA proj (packed bufA -> fp32 bufB); HMMA rnn -> packed bufB
    tproj_kernel<16, 128><<<148, 256, smem_t1>>>((const unsigned*)bufA, B1h, B1l, Bs1, bufB);
    rnnh_kernel<16, 8, true, 128><<<rblocks, 256, smem_rh1>>>(bufB, R1h, R1l, bufB);

    // Layer 2: HMMA proj (packed bufB -> fp32 bufA, N=84); HMMA rnn -> fp32 out
    tproj_kernel<12, 84><<<148, 256, smem_t2>>>((const unsigned*)bufB, B2h, B2l, Bs2, bufA);
    rnnh_kernel<12, 6, false, 84><<<rblocks, 256, smem_rh2>>>(bufA, R2h, R2l, out);
}